// round 14
// baseline (speedup 1.0000x reference)
#include <cuda_runtime.h>
#include <cuda_fp16.h>
#include <math.h>
#include <stdint.h>

// ---------------------------------------------------------------------------
// TransformerEncoder block: H=1024, S1=150, B=128, banded attention (w=20).
// Round 13: R12 + GEMM at 3 CTAs/SM (2-stage cp.async, 64KB smem,
// __launch_bounds__(128,3)). Single-variable change vs R12.
// ---------------------------------------------------------------------------

#define H   1024
#define S1  150
#define NB  128
#define NR  (S1 * NB)      // 19200 rows, r = b*S1 + s
#define WIN 20
#define QT  16             // queries per banded attention block
#define NTILE (((S1 - 1) + QT - 1) / QT)   // 10 tiles over s=1..149

// GEMM tiling
#define KC     64                       // K per stage (halves)
#define TILE2  16384                    // 128 rows * 128 B
#define STG2   (2 * TILE2)              // A + B per stage
#define NST2   2
#define GSMEM  (NST2 * STG2)            // 65536
#define GT     128                      // 4 warps

// Scratch (allocation-free: device globals)
__device__ float  g_pe [S1 * H];
__device__ float  g_x  [NR * H];          // fp32 (residual)
__device__ __half g_xh [NR * H];          // GEMM operand
__device__ __half g_qkvh[NR * 3 * H];     // qkv, fp16
__device__ __half g_atth[NR * H];
__device__ float  g_sa [NR * H];
__device__ float  g_zsa[NR * H];          // fp32 (residual)
__device__ __half g_zsah[NR * H];
__device__ __half g_h1h [NR * H];
__device__ __half g_wqkvT[3 * H * H];     // [N][K] transposed, half
__device__ __half g_woT  [H * H];
__device__ __half g_wm1T [H * H];
__device__ __half g_wm2T [H * H];

// ---------------------------------------------------------------------------
// PTX helpers
// ---------------------------------------------------------------------------
__device__ __forceinline__ void cp16(uint32_t saddr, const void* g) {
    asm volatile("cp.async.cg.shared.global [%0], [%1], 16;"
                 :: "r"(saddr), "l"(g));
}

__device__ __forceinline__ void ldsm4(uint32_t& r0, uint32_t& r1, uint32_t& r2,
                                      uint32_t& r3, uint32_t addr) {
    asm volatile("ldmatrix.sync.aligned.m8n8.x4.shared.b16 {%0,%1,%2,%3}, [%4];"
                 : "=r"(r0), "=r"(r1), "=r"(r2), "=r"(r3) : "r"(addr));
}

__device__ __forceinline__ void mma_f16(float* c, const uint32_t* a,
                                        const uint32_t* b) {
    asm volatile(
        "mma.sync.aligned.m16n8k16.row.col.f32.f16.f16.f32 "
        "{%0,%1,%2,%3},{%4,%5,%6,%7},{%8,%9},{%0,%1,%2,%3};"
        : "+f"(c[0]), "+f"(c[1]), "+f"(c[2]), "+f"(c[3])
        : "r"(a[0]), "r"(a[1]), "r"(a[2]), "r"(a[3]), "r"(b[0]), "r"(b[1]));
}

// ---------------------------------------------------------------------------
// Kernel 0: positional encoding table (fp64 args for exact sin/cos)
// ---------------------------------------------------------------------------
__global__ void pe_kernel() {
    int s = blockIdx.x;
    double pos = 6.283185307179586476925286766559 * (double)s;
    for (int h = threadIdx.x; h < H; h += blockDim.x) {
        int e = h & ~1;
        double dv = exp((double)e * (-log(10000.0) / (double)H));
        double a = pos * dv;
        g_pe[s * H + h] = (float)((h & 1) ? cos(a) : sin(a));
    }
}

// ---------------------------------------------------------------------------
// Fused weight transposes to half: w[K][N] -> wT[N][K]; z selects the matrix.
// ---------------------------------------------------------------------------
__global__ void transpose_all(const float* __restrict__ w0, __half* t0,
                              const float* __restrict__ w1, __half* t1,
                              const float* __restrict__ w2, __half* t2,
                              const float* __restrict__ w3, __half* t3) {
    int zz = blockIdx.z;
    const float* w; __half* wT; int Nc;
    if (zz == 0)      { w = w0; wT = t0; Nc = 3 * H; }
    else if (zz == 1) { w = w1; wT = t1; Nc = H; }
    else if (zz == 2) { w = w2; wT = t2; Nc = H; }
    else              { w = w3; wT = t3; Nc = H; }
    if (blockIdx.x * 32 >= Nc) return;

    __shared__ float t[32][33];
    int bx = blockIdx.x * 32, by = blockIdx.y * 32;
    int x = bx + threadIdx.x;
    for (int j = threadIdx.y; j < 32; j += 8)
        t[j][threadIdx.x] = w[(size_t)(by + j) * Nc + x];
    __syncthreads();
    int xo = by + threadIdx.x;
    for (int j = threadIdx.y; j < 32; j += 8)
        wT[(size_t)(bx + j) * H + xo] = __float2half_rn(t[threadIdx.x][j]);
}

// ---------------------------------------------------------------------------
// Block reduce helper (256 threads = 8 warps)
// ---------------------------------------------------------------------------
__device__ __forceinline__ float2 block_reduce2(float a, float b, float* sh) {
    int lane = threadIdx.x & 31, wid = threadIdx.x >> 5;
#pragma unroll
    for (int o = 16; o; o >>= 1) {
        a += __shfl_xor_sync(0xffffffffu, a, o);
        b += __shfl_xor_sync(0xffffffffu, b, o);
    }
    if (lane == 0) { sh[wid] = a; sh[8 + wid] = b; }
    __syncthreads();
    if (threadIdx.x == 0) {
        float s = 0.f, q = 0.f;
#pragma unroll
        for (int i = 0; i < 8; i++) { s += sh[i]; q += sh[8 + i]; }
        sh[0] = s; sh[8] = q;
    }
    __syncthreads();
    return make_float2(sh[0], sh[8]);
}

// ---------------------------------------------------------------------------
// x = LayerNorm(concat(cls, z^T) + pe); fp32 + half copies. float4 I/O.
// ---------------------------------------------------------------------------
__global__ void build_ln_kernel(const float* __restrict__ z,
                                const float* __restrict__ cls,
                                const float* __restrict__ lg,
                                const float* __restrict__ lb) {
    __shared__ float sh[16];
    int r = blockIdx.x;
    int b = r / S1, s = r % S1;
    int tid = threadIdx.x;
    int h0 = tid * 4;
    const float* src = (s == 0) ? cls : (z + ((size_t)(s - 1) * NB + b) * H);

    float4 sv = *(const float4*)&src[h0];
    float4 pv = *(const float4*)&g_pe[s * H + h0];
    float4 v = make_float4(sv.x + pv.x, sv.y + pv.y, sv.z + pv.z, sv.w + pv.w);
    float sum = v.x + v.y + v.z + v.w;
    float sq  = v.x * v.x + v.y * v.y + v.z * v.z + v.w * v.w;

    float2 t = block_reduce2(sum, sq, sh);
    float mean = t.x * (1.f / H);
    float var  = t.y * (1.f / H) - mean * mean;
    float rstd = rsqrtf(var + 1e-5f);

    float4 gv = *(const float4*)&lg[h0];
    float4 bv = *(const float4*)&lb[h0];
    float4 o = make_float4((v.x - mean) * rstd * gv.x + bv.x,
                           (v.y - mean) * rstd * gv.y + bv.y,
                           (v.z - mean) * rstd * gv.z + bv.z,
                           (v.w - mean) * rstd * gv.w + bv.w);
    *(float4*)&g_x[(size_t)r * H + h0] = o;
    __half2* dh = (__half2*)&g_xh[(size_t)r * H + h0];
    dh[0] = __floats2half2_rn(o.x, o.y);
    dh[1] = __floats2half2_rn(o.z, o.w);
}

// ---------------------------------------------------------------------------
// zsa = LayerNorm(x + sa); fp32 + half copies. float4 I/O.
// ---------------------------------------------------------------------------
__global__ void res_ln_kernel(const float* __restrict__ lg,
                              const float* __restrict__ lb) {
    __shared__ float sh[16];
    int r = blockIdx.x;
    int tid = threadIdx.x;
    int h0 = tid * 4;
    size_t idx = (size_t)r * H + h0;

    float4 xv = *(const float4*)&g_x[idx];
    float4 av = *(const float4*)&g_sa[idx];
    float4 v = make_float4(xv.x + av.x, xv.y + av.y, xv.z + av.z, xv.w + av.w);
    float sum = v.x + v.y + v.z + v.w;
    float sq  = v.x * v.x + v.y * v.y + v.z * v.z + v.w * v.w;

    float2 t = block_reduce2(sum, sq, sh);
    float mean = t.x * (1.f / H);
    float var  = t.y * (1.f / H) - mean * mean;
    float rstd = rsqrtf(var + 1e-5f);

    float4 gv = *(const float4*)&lg[h0];
    float4 bv = *(const float4*)&lb[h0];
    float4 o = make_float4((v.x - mean) * rstd * gv.x + bv.x,
                           (v.y - mean) * rstd * gv.y + bv.y,
                           (v.z - mean) * rstd * gv.z + bv.z,
                           (v.w - mean) * rstd * gv.w + bv.w);
    *(float4*)&g_zsa[idx] = o;
    __half2* dh = (__half2*)&g_zsah[idx];
    dh[0] = __floats2half2_rn(o.x, o.y);
    dh[1] = __floats2half2_rn(o.z, o.w);
}

// ---------------------------------------------------------------------------
// fp16 tensor-core GEMM: C[M,N] = A[M,1024] @ BT[N,1024]^T + bias
// CTA 128x128, 4 warps (64x64 warp tiles), K-chunk 64, XOR-8 swizzle,
// 2-stage cp.async, one barrier per k-iter, 3 CTAs/SM.
//   EPI 0: fp32 out  EPI 1: GELU->half  EPI 2: residual+transpose fp32
//   EPI 3: plain half out
// ---------------------------------------------------------------------------
#define LOADG(kt, stage) do {                                                  \
    uint32_t st_ = (uint32_t)(stage) * STG2;                                   \
    const __half* aS_ = aBase + (kt) * KC;                                     \
    const __half* bS_ = bBase + (kt) * KC;                                     \
    _Pragma("unroll")                                                          \
    for (int i_ = 0; i_ < 8; i_++)                                             \
        cp16(dstA + st_ + (uint32_t)(i_ * 2048), aS_ + i_ * 16 * 1024);        \
    _Pragma("unroll")                                                          \
    for (int i_ = 0; i_ < 8; i_++)                                             \
        cp16(dstB + st_ + (uint32_t)(i_ * 2048), bS_ + i_ * 16 * 1024);        \
    asm volatile("cp.async.commit_group;");                                    \
} while (0)

template <int EPI>
__global__ void __launch_bounds__(GT, 3)
gemm_h(const __half* __restrict__ A, const __half* __restrict__ BT,
       const float* __restrict__ bias, void* __restrict__ Cv, int N,
       const float* __restrict__ res) {
    extern __shared__ __align__(16) uint8_t smem[];
    const int tid = threadIdx.x;
    const int lane = tid & 31, wid = tid >> 5;
    const int mbase = blockIdx.y * 128, nbase = blockIdx.x * 128;
    const uint32_t sbase = (uint32_t)__cvta_generic_to_shared(smem);

    // loader bases (affine; swizzle XOR is per-thread constant)
    const int rowL = tid >> 3, cL = tid & 7;
    const uint32_t xorL = (uint32_t)((cL ^ (rowL & 7)) << 4);
    const __half* aBase = A  + (size_t)(mbase + rowL) * 1024 + cL * 8;
    const __half* bBase = BT + (size_t)(nbase + rowL) * 1024 + cL * 8;
    const uint32_t dstA = sbase + (uint32_t)(rowL * 128) + xorL;
    const uint32_t dstB = dstA + TILE2;

    const int warp_m0 = (wid >> 1) * 64;
    const int warp_n0 = (wid & 1) * 64;

    uint32_t aRow[4], bRow[4];
    int aSw[4], bSw[4];
    const int lr = lane & 15, lc = lane >> 4;
#pragma unroll
    for (int fm = 0; fm < 4; fm++) {
        int row = warp_m0 + fm * 16 + lr;
        aRow[fm] = (uint32_t)row * 128u;
        aSw[fm] = row & 7;
    }
#pragma unroll
    for (int p = 0; p < 4; p++) {
        int row = warp_n0 + p * 16 + lr;
        bRow[p] = (uint32_t)(TILE2 + row * 128);
        bSw[p] = row & 7;
    }

    float acc[4][8][4];
#pragma unroll
    for (int i = 0; i < 4; i++)
#pragma unroll
        for (int j = 0; j < 8; j++)
#pragma unroll
            for (int k = 0; k < 4; k++) acc[i][j][k] = 0.f;

    LOADG(0, 0);

#pragma unroll 1
    for (int kt = 0; kt < 16; kt++) {
        asm volatile("cp.async.wait_group 0;");
        __syncthreads();
        if (kt + 1 < 16) LOADG(kt + 1, (kt + 1) & 1);

        uint32_t so = sbase + (uint32_t)(kt & 1) * STG2;
#pragma unroll
        for (int kk = 0; kk < 4; kk++) {
            uint32_t a[4][4], b[8][2];
#pragma unroll
            for (int fm = 0; fm < 4; fm++)
                ldsm4(a[fm][0], a[fm][1], a[fm][2], a[fm][3],
                      so + aRow[fm] + (uint32_t)(((2 * kk + lc) ^ aSw[fm]) << 4));
#pragma unroll
            for (int p = 0; p < 4; p++) {
                uint32_t r0, r1, r2, r3;
                ldsm4(r0, r1, r2, r3,
                      so + bRow[p] + (uint32_t)(((2 * kk + lc) ^ bSw[p]) << 4));
                b[p * 2][0] = r0;     b[p * 2][1] = r2;
                b[p * 2 + 1][0] = r1; b[p * 2 + 1][1] = r3;
            }
#pragma unroll
            for (int fm = 0; fm < 4; fm++)
#pragma unroll
                for (int fn = 0; fn < 8; fn++)
                    mma_f16(acc[fm][fn], a[fm], b[fn]);
        }
        __syncthreads();
    }

    // epilogue
    const int r4 = lane >> 2, c2 = (lane & 3) * 2;
#pragma unroll
    for (int fm = 0; fm < 4; fm++) {
#pragma unroll
        for (int half_ = 0; half_ < 2; half_++) {
            int m = mbase + warp_m0 + fm * 16 + half_ * 8 + r4;
            int b_ = 0, s_ = 0;
            if (EPI == 2) { b_ = m / S1; s_ = m % S1; }
#pragma unroll
            for (int fn = 0; fn < 8; fn++) {
                int n = nbase + warp_n0 + fn * 8 + c2;
                float2 bv = *(const float2*)&bias[n];
                float v0 = acc[fm][fn][half_ * 2 + 0] + bv.x;
                float v1 = acc[fm][fn][half_ * 2 + 1] + bv.y;
                if (EPI == 0) {
                    *(float2*)&((float*)Cv)[(size_t)m * N + n] =
                        make_float2(v0, v1);
                } else if (EPI == 1) {
                    v0 = 0.5f * v0 * (1.f + erff(v0 * 0.70710678118654752440f));
                    v1 = 0.5f * v1 * (1.f + erff(v1 * 0.70710678118654752440f));
                    *(__half2*)&((__half*)Cv)[(size_t)m * N + n] =
                        __floats2half2_rn(v0, v1);
                } else if (EPI == 3) {
                    *(__half2*)&((__half*)Cv)[(size_t)m * N + n] =
                        __floats2half2_rn(v0, v1);
                } else {
                    size_t ob = ((size_t)s_ * NB + b_) * H + n;
                    float2 rv = *(const float2*)&res[(size_t)m * H + n];
                    *(float2*)&((float*)Cv)[ob] =
                        make_float2(rv.x + v0, rv.y + v1);
                }
            }
        }
    }
}

// ---------------------------------------------------------------------------
// Attention (merged): blockIdx.x < NTILE -> banded query tile (s=1..149);
// blockIdx.x == NTILE -> cls row (s=0, full 150-key window).
// ---------------------------------------------------------------------------
__global__ void attn_kernel() {
    extern __shared__ float dyn[];
    __half* qs = (__half*)dyn;             // [QT][1024] half
    float*  sc = dyn + QT * H / 2;         // [QT][64] (banded) / [160] (cls)
    const int SCW = 64;

    int tile = blockIdx.x, b = blockIdx.y;
    int tid = threadIdx.x, lane = tid & 31, wid = tid >> 5;
    const __half* base = g_qkvh + (size_t)b * S1 * 3 * H;

    if (tile == NTILE) {
        // ---- cls row: q = row 0, keys 0..149 ----
        for (int h = tid; h < H; h += 256) {
            float qv = __half2float(base[h]) * 0.03125f;
            qs[h] = __float2half_rn(qv);
        }
        __syncthreads();

        for (int t = wid; t < S1; t += 8) {
            const __half* krow = base + (size_t)t * 3 * H + H;
            float p = 0.f;
#pragma unroll
            for (int j = 0; j < 8; j++) {
                uint2 kw = *(const uint2*)&krow[lane * 4 + j * 128];
                uint2 qw = *(const uint2*)&qs[lane * 4 + j * 128];
                float2 ka = __half22float2(*(__half2*)&kw.x);
                float2 kb = __half22float2(*(__half2*)&kw.y);
                float2 qa = __half22float2(*(__half2*)&qw.x);
                float2 qb = __half22float2(*(__half2*)&qw.y);
                p += ka.x * qa.x + ka.y * qa.y + kb.x * qb.x + kb.y * qb.y;
            }
#pragma unroll
            for (int o = 16; o; o >>= 1) p += __shfl_xor_sync(0xffffffffu, p, o);
            if (lane == 0) sc[t] = p;
        }
        __syncthreads();

        if (tid < 32) {
            float m = -1e30f;
            for (int i = lane; i < S1; i += 32) m = fmaxf(m, sc[i]);
#pragma unroll
            for (int o = 16; o; o >>= 1)
                m = fmaxf(m, __shfl_xor_sync(0xffffffffu, m, o));
            float ss = 0.f;
            for (int i = lane; i < S1; i += 32) {
                float e = expf(sc[i] - m);
                sc[i] = e; ss += e;
            }
#pragma unroll
            for (int o = 16; o; o >>= 1) ss += __shfl_xor_sync(0xffffffffu, ss, o);
            float inv = 1.f / ss;
            for (int i = lane; i < S1; i += 32) sc[i] *= inv;
        }
        __syncthreads();

        int h0 = tid * 4;
        float4 acc = make_float4(0.f, 0.f, 0.f, 0.f);
        for (int t = 0; t < S1; t++) {
            uint2 raw = *(const uint2*)&base[(size_t)t * 3 * H + 2 * H + h0];
            float2 lo2 = __half22float2(*(__half2*)&raw.x);
            float2 hi2 = __half22float2(*(__half2*)&raw.y);
            float w = sc[t];
            acc.x += w * lo2.x; acc.y += w * lo2.y;
            acc.z += w * hi2.x; acc.w += w * hi2.y;
        }
        __half2* dst = (__half2*)&g_atth[(size_t)(b * S1) * H + h0];
        dst[0] = __floats2half2_rn(acc.x, acc.y);
        dst[1] = __floats2half2_rn(acc.z, acc.w);
        return;
    }

    // ---- banded tile over s = s0 .. s0+nq-1 ----
    int s0 = 1 + tile * QT;
    int nq = min(QT, S1 - s0);

    int lo_u = s0 - WIN; if (lo_u < 0) lo_u = 0;
    int hi_u = s0 + nq - 1 + WIN; if (hi_u > S1) hi_u = S1;

    for (int idx = tid; idx < nq * H; idx += 256) {
        int q = idx >> 10, h = idx & 1023;
        float qv = __half2float(base[(size_t)(s0 + q) * 3 * H + h]) * 0.03125f;
        qs[q * H + h] = __float2half_rn(qv);
    }
    __syncthreads();

    // phase A: scores, 2 keys per warp iteration
    for (int t0 = lo_u + wid * 2; t0 < hi_u; t0 += 16) {
        int t1 = t0 + 1;
        bool has2 = (t1 < hi_u);
        const __half* k0 = base + (size_t)t0 * 3 * H + H;
        const __half* k1 = base + (size_t)(has2 ? t1 : t0) * 3 * H + H;
        float2 kr0[16], kr1[16];
#pragma unroll
        for (int j = 0; j < 8; j++) {
            uint2 w0 = *(const uint2*)&k0[lane * 4 + j * 128];
            uint2 w1 = *(const uint2*)&k1[lane * 4 + j * 128];
            kr0[j * 2]     = __half22float2(*(__half2*)&w0.x);
            kr0[j * 2 + 1] = __half22float2(*(__half2*)&w0.y);
            kr1[j * 2]     = __half22float2(*(__half2*)&w1.x);
            kr1[j * 2 + 1] = __half22float2(*(__half2*)&w1.y);
        }
        for (int q = 0; q < nq; q++) {
            const uint2* qrow = (const uint2*)&qs[q * H];
            float p0 = 0.f, p1 = 0.f;
#pragma unroll
            for (int j = 0; j < 8; j++) {
                uint2 qw = qrow[lane + j * 32];
                float2 qa = __half22float2(*(__half2*)&qw.x);
                float2 qb = __half22float2(*(__half2*)&qw.y);
                p0 += kr0[j * 2].x * qa.x + kr0[j * 2].y * qa.y +
                      kr0[j * 2 + 1].x * qb.x + kr0[j * 2 + 1].y * qb.y;
                p1 += kr1[j * 2].x * qa.x + kr1[j * 2].y * qa.y +
                      kr1[j * 2 + 1].x * qb.x + kr1[j * 2 + 1].y * qb.y;
            }
#pragma unroll
            for (int o = 16; o; o >>= 1) {
                p0 += __shfl_xor_sync(0xffffffffu, p0, o);
                p1 += __shfl_xor_sync(0xffffffffu, p1, o);
            }
            if (lane == 0) {
                sc[q * SCW + (t0 - lo_u)] = p0;
                if (has2) sc[q * SCW + (t1 - lo_u)] = p1;
            }
        }
    }
    __syncthreads();

    // phase B: softmax per query row (warp per row)
    for (int q = wid; q < nq; q += 8) {
        int s = s0 + q;
        int lo = s - WIN; if (lo < 0) lo = 0;
        int hi = s + WIN; if (hi > S1) hi = S1;
        int i0 = lo - lo_u, i1 = hi - lo_u;
        float m = -1e30f;
        for (int i = i0 + lane; i < i1; i += 32) m = fmaxf(m, sc[q * SCW + i]);
#pragma unroll
        for (int o = 16; o; o >>= 1) m = fmaxf(m, __shfl_xor_sync(0xffffffffu, m, o));
        float ss = 0.f;
        for (int i = i0 + lane; i < i1; i += 32) {
            float e = expf(sc[q * SCW + i] - m);
            sc[q * SCW + i] = e; ss += e;
        }
#pragma unroll
        for (int o = 16; o; o >>= 1) ss += __shfl_xor_sync(0xffffffffu, ss, o);
        float inv = 1.f / ss;
        for (int i = i0 + lane; i < i1; i += 32) sc[q * SCW + i] *= inv;
    }
    __syncthreads();

    // phase C: V accumulation. thread owns h0..h0+3 for all queries.
    int h0 = tid * 4;
    float4 acc[QT];
#pragma unroll
    for (int q = 0; q < QT; q++) acc[q] = make_float4(0.f, 0.f, 0.f, 0.f);

    for (int t = lo_u; t < hi_u; t++) {
        uint2 raw = *(const uint2*)&base[(size_t)t * 3 * H + 2 * H + h0];
        float2 lo2 = __half22float2(*(__half2*)&raw.x);
        float2 hi2 = __half22float2(*(__half2*)&raw.y);
        float4 v = make_float4(lo2.x, lo2.y, hi2.x, hi2.y);
#pragma unroll
        for (int q = 0; q < QT; q++) {
            if (q >= nq) break;
            int s = s0 + q;
            bool ok = (t >= s - WIN && t < s + WIN);
            if (ok) {
                float w = sc[q * SCW + (t - lo_u)];
                acc[q].x += w * v.x; acc[q].y += w * v.y;
                acc[q].z += w * v.z; acc[q].w += w * v.w;
            }
        }
    }
#pragma unroll
    for (int q = 0; q < QT; q++) {
        if (q >= nq) break;
        size_t r = (size_t)b * S1 + s0 + q;
        __half2* dst = (__half2*)&g_atth[r * H + h0];
        dst[0] = __floats2half2_rn(acc[q].x, acc[q].y);
        dst[1] = __floats2half2_rn(acc[q].z, acc[q].w);
    }
}

// ---------------------------------------------------------------------------
// Launch
// ---------------------------------------------------------------------------
extern "C" void kernel_launch(void* const* d_in, const int* in_sizes, int n_in,
                              void* d_out, int out_size) {
    (void)in_sizes; (void)n_in; (void)out_size;
    const float* z     = (const float*)d_in[0];
    const float* cls   = (const float*)d_in[1];
    const float* ln_g  = (const float*)d_in[2];
    const float* ln_b  = (const float*)d_in[3];
    const float* w_qkv = (const float*)d_in[4];
    const float* b_qkv = (const float*)d_in[5];
    const float* w_o   = (const float*)d_in[6];
    const float* b_o   = (const float*)d_in[7];
    const float* w_m1  = (const float*)d_in[8];
    const float* b_m1  = (const float*)d_in[9];
    const float* w_m2  = (const float*)d_in[10];
    const float* b_m2  = (const float*)d_in[11];
    float* out = (float*)d_out;

    __half *pxh, *pqkvh, *patth, *pzsah, *ph1h, *pwqkvT, *pwoT, *pwm1T, *pwm2T;
    float  *psa, *pzsa;
    cudaGetSymbolAddress((void**)&pxh,   g_xh);
    cudaGetSymbolAddress((void**)&pqkvh, g_qkvh);
    cudaGetSymbolAddress((void**)&patth, g_atth);
    cudaGetSymbolAddress((void**)&psa,   g_sa);
    cudaGetSymbolAddress((void**)&pzsa,  g_zsa);
    cudaGetSymbolAddress((void**)&pzsah, g_zsah);
    cudaGetSymbolAddress((void**)&ph1h,  g_h1h);
    cudaGetSymbolAddress((void**)&pwqkvT, g_wqkvT);
    cudaGetSymbolAddress((void**)&pwoT,   g_woT);
    cudaGetSymbolAddress((void**)&pwm1T,  g_wm1T);
    cudaGetSymbolAddress((void**)&pwm2T,  g_wm2T);

    const int ATTN_SMEM = QT * H * 2 + QT * 64 * 4;   // half q + fp32 scores
    static int attr_set = 0;
    if (!attr_set) {
        cudaFuncSetAttribute(attn_kernel,
                             cudaFuncAttributeMaxDynamicSharedMemorySize,
                             ATTN_SMEM);
        cudaFuncSetAttribute(gemm_h<0>,
                             cudaFuncAttributeMaxDynamicSharedMemorySize, GSMEM);
        cudaFuncSetAttribute(gemm_h<1>,
                             cudaFuncAttributeMaxDynamicSharedMemorySize, GSMEM);
        cudaFuncSetAttribute(gemm_h<2>,
                             cudaFuncAttributeMaxDynamicSharedMemorySize, GSMEM);
        cudaFuncSetAttribute(gemm_h<3>,
                             cudaFuncAttributeMaxDynamicSharedMemorySize, GSMEM);
        attr_set = 1;
    }

    pe_kernel<<<S1, 256>>>();
    transpose_all<<<dim3(96, 32, 4), dim3(32, 8)>>>(w_qkv, pwqkvT, w_o, pwoT,
                                                    w_m1, pwm1T, w_m2, pwm2T);
    build_ln_kernel<<<NR, 256>>>(z, cls, ln_g, ln_b);

    // qkv = x @ w_qkv + b_qkv   (half out)
    gemm_h<3><<<dim3(3 * H / 128, NR / 128), GT, GSMEM>>>(pxh, pwqkvT, b_qkv, pqkvh, 3 * H, nullptr);
    // banded tiles + cls row in one launch
    attn_kernel<<<dim3(NTILE + 1, NB), 256, ATTN_SMEM>>>();
    // sa = att @ w_o + b_o      (fp32 out)
    gemm_h<0><<<dim3(H / 128, NR / 128), GT, GSMEM>>>(patth, pwoT, b_o, psa, H, nullptr);
    res_ln_kernel<<<NR, 256>>>(ln_g, ln_b);
    // h1 = gelu(zsa @ w_m1 + b_m1)  (half out)
    gemm_h<1><<<dim3(H / 128, NR / 128), GT, GSMEM>>>(pzsah, pwm1T, b_m1, ph1h, H, nullptr);
    // out = transpose(zsa + h1 @ w_m2 + b_m2)
    gemm_h<2><<<dim3(H / 128, NR / 128), GT, GSMEM>>>(ph1h, pwm2T, b_m2, out, H, pzsa);
}

// round 15
// speedup vs baseline: 1.0401x; 1.0401x over previous
#include <cuda_runtime.h>
#include <cuda_fp16.h>
#include <math.h>
#include <stdint.h>

// ---------------------------------------------------------------------------
// TransformerEncoder block: H=1024, S1=150, B=128, banded attention (w=20).
// Round 14: R12 GEMM config restored (3-stage, 2 CTAs/SM); ALL intermediate
// tensors fp16 (residuals included) -> ~310 MB less traffic in LN/epilogues.
// ---------------------------------------------------------------------------

#define H   1024
#define S1  150
#define NB  128
#define NR  (S1 * NB)      // 19200 rows, r = b*S1 + s
#define WIN 20
#define QT  16             // queries per banded attention block
#define NTILE (((S1 - 1) + QT - 1) / QT)   // 10 tiles over s=1..149

// GEMM tiling (R12 proven config)
#define KC     64                       // K per stage (halves)
#define TILE2  16384                    // 128 rows * 128 B
#define STG2   (2 * TILE2)              // A + B per stage
#define NST2   3
#define GSMEM  (NST2 * STG2)            // 98304
#define GT     128                      // 4 warps

// Scratch (allocation-free: device globals) — all fp16
__device__ float  g_pe [S1 * H];
__device__ __half g_xh [NR * H];          // LN1 output (operand + residual)
__device__ __half g_qkvh[NR * 3 * H];     // qkv
__device__ __half g_atth[NR * H];         // attention output
__device__ __half g_sah [NR * H];         // w_o projection
__device__ __half g_zsah[NR * H];         // LN2 output (operand + residual)
__device__ __half g_h1h [NR * H];         // gelu(m1)
__device__ __half g_wqkvT[3 * H * H];     // [N][K] transposed, half
__device__ __half g_woT  [H * H];
__device__ __half g_wm1T [H * H];
__device__ __half g_wm2T [H * H];

// ---------------------------------------------------------------------------
// PTX helpers
// ---------------------------------------------------------------------------
__device__ __forceinline__ void cp16(uint32_t saddr, const void* g) {
    asm volatile("cp.async.cg.shared.global [%0], [%1], 16;"
                 :: "r"(saddr), "l"(g));
}

__device__ __forceinline__ void ldsm4(uint32_t& r0, uint32_t& r1, uint32_t& r2,
                                      uint32_t& r3, uint32_t addr) {
    asm volatile("ldmatrix.sync.aligned.m8n8.x4.shared.b16 {%0,%1,%2,%3}, [%4];"
                 : "=r"(r0), "=r"(r1), "=r"(r2), "=r"(r3) : "r"(addr));
}

__device__ __forceinline__ void mma_f16(float* c, const uint32_t* a,
                                        const uint32_t* b) {
    asm volatile(
        "mma.sync.aligned.m16n8k16.row.col.f32.f16.f16.f32 "
        "{%0,%1,%2,%3},{%4,%5,%6,%7},{%8,%9},{%0,%1,%2,%3};"
        : "+f"(c[0]), "+f"(c[1]), "+f"(c[2]), "+f"(c[3])
        : "r"(a[0]), "r"(a[1]), "r"(a[2]), "r"(a[3]), "r"(b[0]), "r"(b[1]));
}

// ---------------------------------------------------------------------------
// Kernel 0: positional encoding table (fp64 args for exact sin/cos)
// ---------------------------------------------------------------------------
__global__ void pe_kernel() {
    int s = blockIdx.x;
    double pos = 6.283185307179586476925286766559 * (double)s;
    for (int h = threadIdx.x; h < H; h += blockDim.x) {
        int e = h & ~1;
        double dv = exp((double)e * (-log(10000.0) / (double)H));
        double a = pos * dv;
        g_pe[s * H + h] = (float)((h & 1) ? cos(a) : sin(a));
    }
}

// ---------------------------------------------------------------------------
// Fused weight transposes to half: w[K][N] -> wT[N][K]; z selects the matrix.
// ---------------------------------------------------------------------------
__global__ void transpose_all(const float* __restrict__ w0, __half* t0,
                              const float* __restrict__ w1, __half* t1,
                              const float* __restrict__ w2, __half* t2,
                              const float* __restrict__ w3, __half* t3) {
    int zz = blockIdx.z;
    const float* w; __half* wT; int Nc;
    if (zz == 0)      { w = w0; wT = t0; Nc = 3 * H; }
    else if (zz == 1) { w = w1; wT = t1; Nc = H; }
    else if (zz == 2) { w = w2; wT = t2; Nc = H; }
    else              { w = w3; wT = t3; Nc = H; }
    if (blockIdx.x * 32 >= Nc) return;

    __shared__ float t[32][33];
    int bx = blockIdx.x * 32, by = blockIdx.y * 32;
    int x = bx + threadIdx.x;
    for (int j = threadIdx.y; j < 32; j += 8)
        t[j][threadIdx.x] = w[(size_t)(by + j) * Nc + x];
    __syncthreads();
    int xo = by + threadIdx.x;
    for (int j = threadIdx.y; j < 32; j += 8)
        wT[(size_t)(bx + j) * H + xo] = __float2half_rn(t[threadIdx.x][j]);
}

// ---------------------------------------------------------------------------
// Block reduce helper (256 threads = 8 warps)
// ---------------------------------------------------------------------------
__device__ __forceinline__ float2 block_reduce2(float a, float b, float* sh) {
    int lane = threadIdx.x & 31, wid = threadIdx.x >> 5;
#pragma unroll
    for (int o = 16; o; o >>= 1) {
        a += __shfl_xor_sync(0xffffffffu, a, o);
        b += __shfl_xor_sync(0xffffffffu, b, o);
    }
    if (lane == 0) { sh[wid] = a; sh[8 + wid] = b; }
    __syncthreads();
    if (threadIdx.x == 0) {
        float s = 0.f, q = 0.f;
#pragma unroll
        for (int i = 0; i < 8; i++) { s += sh[i]; q += sh[8 + i]; }
        sh[0] = s; sh[8] = q;
    }
    __syncthreads();
    return make_float2(sh[0], sh[8]);
}

// ---------------------------------------------------------------------------
// x = LayerNorm(concat(cls, z^T) + pe); half output only. float4 I/O.
// ---------------------------------------------------------------------------
__global__ void build_ln_kernel(const float* __restrict__ z,
                                const float* __restrict__ cls,
                                const float* __restrict__ lg,
                                const float* __restrict__ lb) {
    __shared__ float sh[16];
    int r = blockIdx.x;
    int b = r / S1, s = r % S1;
    int tid = threadIdx.x;
    int h0 = tid * 4;
    const float* src = (s == 0) ? cls : (z + ((size_t)(s - 1) * NB + b) * H);

    float4 sv = *(const float4*)&src[h0];
    float4 pv = *(const float4*)&g_pe[s * H + h0];
    float4 v = make_float4(sv.x + pv.x, sv.y + pv.y, sv.z + pv.z, sv.w + pv.w);
    float sum = v.x + v.y + v.z + v.w;
    float sq  = v.x * v.x + v.y * v.y + v.z * v.z + v.w * v.w;

    float2 t = block_reduce2(sum, sq, sh);
    float mean = t.x * (1.f / H);
    float var  = t.y * (1.f / H) - mean * mean;
    float rstd = rsqrtf(var + 1e-5f);

    float4 gv = *(const float4*)&lg[h0];
    float4 bv = *(const float4*)&lb[h0];
    __half2* dh = (__half2*)&g_xh[(size_t)r * H + h0];
    dh[0] = __floats2half2_rn((v.x - mean) * rstd * gv.x + bv.x,
                              (v.y - mean) * rstd * gv.y + bv.y);
    dh[1] = __floats2half2_rn((v.z - mean) * rstd * gv.z + bv.z,
                              (v.w - mean) * rstd * gv.w + bv.w);
}

// ---------------------------------------------------------------------------
// zsa = LayerNorm(xh + sah); half in, half out.
// ---------------------------------------------------------------------------
__global__ void res_ln_kernel(const float* __restrict__ lg,
                              const float* __restrict__ lb) {
    __shared__ float sh[16];
    int r = blockIdx.x;
    int tid = threadIdx.x;
    int h0 = tid * 4;
    size_t idx = (size_t)r * H + h0;

    uint2 xr = *(const uint2*)&g_xh[idx];
    uint2 ar = *(const uint2*)&g_sah[idx];
    float2 x0 = __half22float2(*(__half2*)&xr.x);
    float2 x1 = __half22float2(*(__half2*)&xr.y);
    float2 a0 = __half22float2(*(__half2*)&ar.x);
    float2 a1 = __half22float2(*(__half2*)&ar.y);
    float4 v = make_float4(x0.x + a0.x, x0.y + a0.y, x1.x + a1.x, x1.y + a1.y);
    float sum = v.x + v.y + v.z + v.w;
    float sq  = v.x * v.x + v.y * v.y + v.z * v.z + v.w * v.w;

    float2 t = block_reduce2(sum, sq, sh);
    float mean = t.x * (1.f / H);
    float var  = t.y * (1.f / H) - mean * mean;
    float rstd = rsqrtf(var + 1e-5f);

    float4 gv = *(const float4*)&lg[h0];
    float4 bv = *(const float4*)&lb[h0];
    __half2* dh = (__half2*)&g_zsah[idx];
    dh[0] = __floats2half2_rn((v.x - mean) * rstd * gv.x + bv.x,
                              (v.y - mean) * rstd * gv.y + bv.y);
    dh[1] = __floats2half2_rn((v.z - mean) * rstd * gv.z + bv.z,
                              (v.w - mean) * rstd * gv.w + bv.w);
}

// ---------------------------------------------------------------------------
// fp16 tensor-core GEMM: C[M,N] = A[M,1024] @ BT[N,1024]^T + bias
// CTA 128x128, 4 warps (64x64 warp tiles), K-chunk 64, XOR-8 swizzle,
// 3-stage cp.async, one barrier per k-iter, 2 CTAs/SM (R12 config).
//   EPI 1: GELU->half  EPI 2: half residual + transpose, fp32 out
//   EPI 3: plain half out
// ---------------------------------------------------------------------------
#define LOADG(kt, stage) do {                                                  \
    uint32_t st_ = (uint32_t)(stage) * STG2;                                   \
    const __half* aS_ = aBase + (kt) * KC;                                     \
    const __half* bS_ = bBase + (kt) * KC;                                     \
    _Pragma("unroll")                                                          \
    for (int i_ = 0; i_ < 8; i_++)                                             \
        cp16(dstA + st_ + (uint32_t)(i_ * 2048), aS_ + i_ * 16 * 1024);        \
    _Pragma("unroll")                                                          \
    for (int i_ = 0; i_ < 8; i_++)                                             \
        cp16(dstB + st_ + (uint32_t)(i_ * 2048), bS_ + i_ * 16 * 1024);        \
    asm volatile("cp.async.commit_group;");                                    \
} while (0)

template <int EPI>
__global__ void __launch_bounds__(GT, 2)
gemm_h(const __half* __restrict__ A, const __half* __restrict__ BT,
       const float* __restrict__ bias, void* __restrict__ Cv, int N,
       const __half* __restrict__ res) {
    extern __shared__ __align__(16) uint8_t smem[];
    const int tid = threadIdx.x;
    const int lane = tid & 31, wid = tid >> 5;
    const int mbase = blockIdx.y * 128, nbase = blockIdx.x * 128;
    const uint32_t sbase = (uint32_t)__cvta_generic_to_shared(smem);

    // loader bases (affine; swizzle XOR is per-thread constant)
    const int rowL = tid >> 3, cL = tid & 7;
    const uint32_t xorL = (uint32_t)((cL ^ (rowL & 7)) << 4);
    const __half* aBase = A  + (size_t)(mbase + rowL) * 1024 + cL * 8;
    const __half* bBase = BT + (size_t)(nbase + rowL) * 1024 + cL * 8;
    const uint32_t dstA = sbase + (uint32_t)(rowL * 128) + xorL;
    const uint32_t dstB = dstA + TILE2;

    const int warp_m0 = (wid >> 1) * 64;
    const int warp_n0 = (wid & 1) * 64;

    uint32_t aRow[4], bRow[4];
    int aSw[4], bSw[4];
    const int lr = lane & 15, lc = lane >> 4;
#pragma unroll
    for (int fm = 0; fm < 4; fm++) {
        int row = warp_m0 + fm * 16 + lr;
        aRow[fm] = (uint32_t)row * 128u;
        aSw[fm] = row & 7;
    }
#pragma unroll
    for (int p = 0; p < 4; p++) {
        int row = warp_n0 + p * 16 + lr;
        bRow[p] = (uint32_t)(TILE2 + row * 128);
        bSw[p] = row & 7;
    }

    float acc[4][8][4];
#pragma unroll
    for (int i = 0; i < 4; i++)
#pragma unroll
        for (int j = 0; j < 8; j++)
#pragma unroll
            for (int k = 0; k < 4; k++) acc[i][j][k] = 0.f;

    LOADG(0, 0);
    LOADG(1, 1);

#pragma unroll 1
    for (int kt = 0; kt < 16; kt++) {
        if (kt < 15)
            asm volatile("cp.async.wait_group 1;");
        else
            asm volatile("cp.async.wait_group 0;");
        __syncthreads();
        if (kt + 2 < 16) LOADG(kt + 2, (kt + 2) % NST2);

        uint32_t so = sbase + (uint32_t)(kt % NST2) * STG2;
#pragma unroll
        for (int kk = 0; kk < 4; kk++) {
            uint32_t a[4][4], b[8][2];
#pragma unroll
            for (int fm = 0; fm < 4; fm++)
                ldsm4(a[fm][0], a[fm][1], a[fm][2], a[fm][3],
                      so + aRow[fm] + (uint32_t)(((2 * kk + lc) ^ aSw[fm]) << 4));
#pragma unroll
            for (int p = 0; p < 4; p++) {
                uint32_t r0, r1, r2, r3;
                ldsm4(r0, r1, r2, r3,
                      so + bRow[p] + (uint32_t)(((2 * kk + lc) ^ bSw[p]) << 4));
                b[p * 2][0] = r0;     b[p * 2][1] = r2;
                b[p * 2 + 1][0] = r1; b[p * 2 + 1][1] = r3;
            }
#pragma unroll
            for (int fm = 0; fm < 4; fm++)
#pragma unroll
                for (int fn = 0; fn < 8; fn++)
                    mma_f16(acc[fm][fn], a[fm], b[fn]);
        }
    }

    // epilogue
    const int r4 = lane >> 2, c2 = (lane & 3) * 2;
#pragma unroll
    for (int fm = 0; fm < 4; fm++) {
#pragma unroll
        for (int half_ = 0; half_ < 2; half_++) {
            int m = mbase + warp_m0 + fm * 16 + half_ * 8 + r4;
            int b_ = 0, s_ = 0;
            if (EPI == 2) { b_ = m / S1; s_ = m % S1; }
#pragma unroll
            for (int fn = 0; fn < 8; fn++) {
                int n = nbase + warp_n0 + fn * 8 + c2;
                float2 bv = *(const float2*)&bias[n];
                float v0 = acc[fm][fn][half_ * 2 + 0] + bv.x;
                float v1 = acc[fm][fn][half_ * 2 + 1] + bv.y;
                if (EPI == 1) {
                    v0 = 0.5f * v0 * (1.f + erff(v0 * 0.70710678118654752440f));
                    v1 = 0.5f * v1 * (1.f + erff(v1 * 0.70710678118654752440f));
                    *(__half2*)&((__half*)Cv)[(size_t)m * N + n] =
                        __floats2half2_rn(v0, v1);
                } else if (EPI == 3) {
                    *(__half2*)&((__half*)Cv)[(size_t)m * N + n] =
                        __floats2half2_rn(v0, v1);
                } else {
                    size_t ob = ((size_t)s_ * NB + b_) * H + n;
                    __half2 rh = *(const __half2*)&res[(size_t)m * H + n];
                    float2 rv = __half22float2(rh);
                    *(float2*)&((float*)Cv)[ob] =
                        make_float2(rv.x + v0, rv.y + v1);
                }
            }
        }
    }
}

// ---------------------------------------------------------------------------
// Attention (merged): blockIdx.x < NTILE -> banded query tile (s=1..149);
// blockIdx.x == NTILE -> cls row (s=0, full 150-key window).
// ---------------------------------------------------------------------------
__global__ void attn_kernel() {
    extern __shared__ float dyn[];
    __half* qs = (__half*)dyn;             // [QT][1024] half
    float*  sc = dyn + QT * H / 2;         // [QT][64] (banded) / [160] (cls)
    const int SCW = 64;

    int tile = blockIdx.x, b = blockIdx.y;
    int tid = threadIdx.x, lane = tid & 31, wid = tid >> 5;
    const __half* base = g_qkvh + (size_t)b * S1 * 3 * H;

    if (tile == NTILE) {
        // ---- cls row: q = row 0, keys 0..149 ----
        for (int h = tid; h < H; h += 256) {
            float qv = __half2float(base[h]) * 0.03125f;
            qs[h] = __float2half_rn(qv);
        }
        __syncthreads();

        for (int t = wid; t < S1; t += 8) {
            const __half* krow = base + (size_t)t * 3 * H + H;
            float p = 0.f;
#pragma unroll
            for (int j = 0; j < 8; j++) {
                uint2 kw = *(const uint2*)&krow[lane * 4 + j * 128];
                uint2 qw = *(const uint2*)&qs[lane * 4 + j * 128];
                float2 ka = __half22float2(*(__half2*)&kw.x);
                float2 kb = __half22float2(*(__half2*)&kw.y);
                float2 qa = __half22float2(*(__half2*)&qw.x);
                float2 qb = __half22float2(*(__half2*)&qw.y);
                p += ka.x * qa.x + ka.y * qa.y + kb.x * qb.x + kb.y * qb.y;
            }
#pragma unroll
            for (int o = 16; o; o >>= 1) p += __shfl_xor_sync(0xffffffffu, p, o);
            if (lane == 0) sc[t] = p;
        }
        __syncthreads();

        if (tid < 32) {
            float m = -1e30f;
            for (int i = lane; i < S1; i += 32) m = fmaxf(m, sc[i]);
#pragma unroll
            for (int o = 16; o; o >>= 1)
                m = fmaxf(m, __shfl_xor_sync(0xffffffffu, m, o));
            float ss = 0.f;
            for (int i = lane; i < S1; i += 32) {
                float e = expf(sc[i] - m);
                sc[i] = e; ss += e;
            }
#pragma unroll
            for (int o = 16; o; o >>= 1) ss += __shfl_xor_sync(0xffffffffu, ss, o);
            float inv = 1.f / ss;
            for (int i = lane; i < S1; i += 32) sc[i] *= inv;
        }
        __syncthreads();

        int h0 = tid * 4;
        float4 acc = make_float4(0.f, 0.f, 0.f, 0.f);
        for (int t = 0; t < S1; t++) {
            uint2 raw = *(const uint2*)&base[(size_t)t * 3 * H + 2 * H + h0];
            float2 lo2 = __half22float2(*(__half2*)&raw.x);
            float2 hi2 = __half22float2(*(__half2*)&raw.y);
            float w = sc[t];
            acc.x += w * lo2.x; acc.y += w * lo2.y;
            acc.z += w * hi2.x; acc.w += w * hi2.y;
        }
        __half2* dst = (__half2*)&g_atth[(size_t)(b * S1) * H + h0];
        dst[0] = __floats2half2_rn(acc.x, acc.y);
        dst[1] = __floats2half2_rn(acc.z, acc.w);
        return;
    }

    // ---- banded tile over s = s0 .. s0+nq-1 ----
    int s0 = 1 + tile * QT;
    int nq = min(QT, S1 - s0);

    int lo_u = s0 - WIN; if (lo_u < 0) lo_u = 0;
    int hi_u = s0 + nq - 1 + WIN; if (hi_u > S1) hi_u = S1;

    for (int idx = tid; idx < nq * H; idx += 256) {
        int q = idx >> 10, h = idx & 1023;
        float qv = __half2float(base[(size_t)(s0 + q) * 3 * H + h]) * 0.03125f;
        qs[q * H + h] = __float2half_rn(qv);
    }
    __syncthreads();

    // phase A: scores, 2 keys per warp iteration
    for (int t0 = lo_u + wid * 2; t0 < hi_u; t0 += 16) {
        int t1 = t0 + 1;
        bool has2 = (t1 < hi_u);
        const __half* k0 = base + (size_t)t0 * 3 * H + H;
        const __half* k1 = base + (size_t)(has2 ? t1 : t0) * 3 * H + H;
        float2 kr0[16], kr1[16];
#pragma unroll
        for (int j = 0; j < 8; j++) {
            uint2 w0 = *(const uint2*)&k0[lane * 4 + j * 128];
            uint2 w1 = *(const uint2*)&k1[lane * 4 + j * 128];
            kr0[j * 2]     = __half22float2(*(__half2*)&w0.x);
            kr0[j * 2 + 1] = __half22float2(*(__half2*)&w0.y);
            kr1[j * 2]     = __half22float2(*(__half2*)&w1.x);
            kr1[j * 2 + 1] = __half22float2(*(__half2*)&w1.y);
        }
        for (int q = 0; q < nq; q++) {
            const uint2* qrow = (const uint2*)&qs[q * H];
            float p0 = 0.f, p1 = 0.f;
#pragma unroll
            for (int j = 0; j < 8; j++) {
                uint2 qw = qrow[lane + j * 32];
                float2 qa = __half22float2(*(__half2*)&qw.x);
                float2 qb = __half22float2(*(__half2*)&qw.y);
                p0 += kr0[j * 2].x * qa.x + kr0[j * 2].y * qa.y +
                      kr0[j * 2 + 1].x * qb.x + kr0[j * 2 + 1].y * qb.y;
                p1 += kr1[j * 2].x * qa.x + kr1[j * 2].y * qa.y +
                      kr1[j * 2 + 1].x * qb.x + kr1[j * 2 + 1].y * qb.y;
            }
#pragma unroll
            for (int o = 16; o; o >>= 1) {
                p0 += __shfl_xor_sync(0xffffffffu, p0, o);
                p1 += __shfl_xor_sync(0xffffffffu, p1, o);
            }
            if (lane == 0) {
                sc[q * SCW + (t0 - lo_u)] = p0;
                if (has2) sc[q * SCW + (t1 - lo_u)] = p1;
            }
        }
    }
    __syncthreads();

    // phase B: softmax per query row (warp per row)
    for (int q = wid; q < nq; q += 8) {
        int s = s0 + q;
        int lo = s - WIN; if (lo < 0) lo = 0;
        int hi = s + WIN; if (hi > S1) hi = S1;
        int i0 = lo - lo_u, i1 = hi - lo_u;
        float m = -1e30f;
        for (int i = i0 + lane; i < i1; i += 32) m = fmaxf(m, sc[q * SCW + i]);
#pragma unroll
        for (int o = 16; o; o >>= 1) m = fmaxf(m, __shfl_xor_sync(0xffffffffu, m, o));
        float ss = 0.f;
        for (int i = i0 + lane; i < i1; i += 32) {
            float e = expf(sc[q * SCW + i] - m);
            sc[q * SCW + i] = e; ss += e;
        }
#pragma unroll
        for (int o = 16; o; o >>= 1) ss += __shfl_xor_sync(0xffffffffu, ss, o);
        float inv = 1.f / ss;
        for (int i = i0 + lane; i < i1; i += 32) sc[q * SCW + i] *= inv;
    }
    __syncthreads();

    // phase C: V accumulation. thread owns h0..h0+3 for all queries.
    int h0 = tid * 4;
    float4 acc[QT];
#pragma unroll
    for (int q = 0; q < QT; q++) acc[q] = make_float4(0.f, 0.f, 0.f, 0.f);

    for (int t = lo_u; t < hi_u; t++) {
        uint2 raw = *(const uint2*)&base[(size_t)t * 3 * H + 2 * H + h0];
        float2 lo2 = __half22float2(*(__half2*)&raw.x);
        float2 hi2 = __half22float2(*(__half2*)&raw.y);
        float4 v = make_float4(lo2.x, lo2.y, hi2.x, hi2.y);
#pragma unroll
        for (int q = 0; q < QT; q++) {
            if (q >= nq) break;
            int s = s0 + q;
            bool ok = (t >= s - WIN && t < s + WIN);
            if (ok) {
                float w = sc[q * SCW + (t - lo_u)];
                acc[q].x += w * v.x; acc[q].y += w * v.y;
                acc[q].z += w * v.z; acc[q].w += w * v.w;
            }
        }
    }
#pragma unroll
    for (int q = 0; q < QT; q++) {
        if (q >= nq) break;
        size_t r = (size_t)b * S1 + s0 + q;
        __half2* dst = (__half2*)&g_atth[r * H + h0];
        dst[0] = __floats2half2_rn(acc[q].x, acc[q].y);
        dst[1] = __floats2half2_rn(acc[q].z, acc[q].w);
    }
}

// ---------------------------------------------------------------------------
// Launch
// ---------------------------------------------------------------------------
extern "C" void kernel_launch(void* const* d_in, const int* in_sizes, int n_in,
                              void* d_out, int out_size) {
    (void)in_sizes; (void)n_in; (void)out_size;
    const float* z     = (const float*)d_in[0];
    const float* cls   = (const float*)d_in[1];
    const float* ln_g  = (const float*)d_in[2];
    const float* ln_b  = (const float*)d_in[3];
    const float* w_qkv = (const float*)d_in[4];
    const float* b_qkv = (const float*)d_in[5];
    const float* w_o   = (const float*)d_in[6];
    const float* b_o   = (const float*)d_in[7];
    const float* w_m1  = (const float*)d_in[8];
    const float* b_m1  = (const float*)d_in[9];
    const float* w_m2  = (const float*)d_in[10];
    const float* b_m2  = (const float*)d_in[11];
    float* out = (float*)d_out;

    __half *pxh, *pqkvh, *patth, *psah, *pzsah, *ph1h;
    __half *pwqkvT, *pwoT, *pwm1T, *pwm2T;
    cudaGetSymbolAddress((void**)&pxh,   g_xh);
    cudaGetSymbolAddress((void**)&pqkvh, g_qkvh);
    cudaGetSymbolAddress((void**)&patth, g_atth);
    cudaGetSymbolAddress((void**)&psah,  g_sah);
    cudaGetSymbolAddress((void**)&pzsah, g_zsah);
    cudaGetSymbolAddress((void**)&ph1h,  g_h1h);
    cudaGetSymbolAddress((void**)&pwqkvT, g_wqkvT);
    cudaGetSymbolAddress((void**)&pwoT,   g_woT);
    cudaGetSymbolAddress((void**)&pwm1T,  g_wm1T);
    cudaGetSymbolAddress((void**)&pwm2T,  g_wm2T);

    const int ATTN_SMEM = QT * H * 2 + QT * 64 * 4;   // half q + fp32 scores
    static int attr_set = 0;
    if (!attr_set) {
        cudaFuncSetAttribute(attn_kernel,
                             cudaFuncAttributeMaxDynamicSharedMemorySize,
                             ATTN_SMEM);
        cudaFuncSetAttribute(gemm_h<1>,
                             cudaFuncAttributeMaxDynamicSharedMemorySize, GSMEM);
        cudaFuncSetAttribute(gemm_h<2>,
                             cudaFuncAttributeMaxDynamicSharedMemorySize, GSMEM);
        cudaFuncSetAttribute(gemm_h<3>,
                             cudaFuncAttributeMaxDynamicSharedMemorySize, GSMEM);
        attr_set = 1;
    }

    pe_kernel<<<S1, 256>>>();
    transpose_all<<<dim3(96, 32, 4), dim3(32, 8)>>>(w_qkv, pwqkvT, w_o, pwoT,
                                                    w_m1, pwm1T, w_m2, pwm2T);
    build_ln_kernel<<<NR, 256>>>(z, cls, ln_g, ln_b);

    // qkv = x @ w_qkv + b_qkv   (half out)
    gemm_h<3><<<dim3(3 * H / 128, NR / 128), GT, GSMEM>>>(pxh, pwqkvT, b_qkv, pqkvh, 3 * H, nullptr);
    // banded tiles + cls row in one launch
    attn_kernel<<<dim3(NTILE + 1, NB), 256, ATTN_SMEM>>>();
    // sa = att @ w_o + b_o      (half out)
    gemm_h<3><<<dim3(H / 128, NR / 128), GT, GSMEM>>>(patth, pwoT, b_o, psah, H, nullptr);
    res_ln_kernel<<<NR, 256>>>(ln_g, ln_b);
    // h1 = gelu(zsa @ w_m1 + b_m1)  (half out)
    gemm_h<1><<<dim3(H / 128, NR / 128), GT, GSMEM>>>(pzsah, pwm1T, b_m1, ph1h, H, nullptr);
    // out = transpose(zsah + h1 @ w_m2 + b_m2)  (fp32 out, half residual)
    gemm_h<2><<<dim3(H / 128, NR / 128), GT, GSMEM>>>(ph1h, pwm2T, b_m2, out, H, pzsah);
}

// round 16
// speedup vs baseline: 1.0402x; 1.0001x over previous
#include <cuda_runtime.h>
#include <cuda_fp16.h>
#include <math.h>
#include <stdint.h>

// ---------------------------------------------------------------------------
// TransformerEncoder block: H=1024, S1=150, B=128, banded attention (w=20).
// Round 15: R14 + global row layout r' = s*NB + b for all intermediates.
// Final GEMM epilogue becomes fully coalesced (output already in (s,b,h)).
// ---------------------------------------------------------------------------

#define H   1024
#define S1  150
#define NB  128
#define NR  (S1 * NB)      // 19200 rows, r' = s*NB + b
#define WIN 20
#define QT  16             // queries per banded attention block
#define NTILE (((S1 - 1) + QT - 1) / QT)   // 10 tiles over s=1..149

// GEMM tiling (R12 proven config)
#define KC     64                       // K per stage (halves)
#define TILE2  16384                    // 128 rows * 128 B
#define STG2   (2 * TILE2)              // A + B per stage
#define NST2   3
#define GSMEM  (NST2 * STG2)            // 98304
#define GT     128                      // 4 warps

// Scratch (allocation-free: device globals) — all fp16, rows r' = s*NB+b
__device__ float  g_pe [S1 * H];
__device__ __half g_xh [NR * H];          // LN1 output (operand + residual)
__device__ __half g_qkvh[NR * 3 * H];     // qkv
__device__ __half g_atth[NR * H];         // attention output
__device__ __half g_sah [NR * H];         // w_o projection
__device__ __half g_zsah[NR * H];         // LN2 output (operand + residual)
__device__ __half g_h1h [NR * H];         // gelu(m1)
__device__ __half g_wqkvT[3 * H * H];     // [N][K] transposed, half
__device__ __half g_woT  [H * H];
__device__ __half g_wm1T [H * H];
__device__ __half g_wm2T [H * H];

// ---------------------------------------------------------------------------
// PTX helpers
// ---------------------------------------------------------------------------
__device__ __forceinline__ void cp16(uint32_t saddr, const void* g) {
    asm volatile("cp.async.cg.shared.global [%0], [%1], 16;"
                 :: "r"(saddr), "l"(g));
}

__device__ __forceinline__ void ldsm4(uint32_t& r0, uint32_t& r1, uint32_t& r2,
                                      uint32_t& r3, uint32_t addr) {
    asm volatile("ldmatrix.sync.aligned.m8n8.x4.shared.b16 {%0,%1,%2,%3}, [%4];"
                 : "=r"(r0), "=r"(r1), "=r"(r2), "=r"(r3) : "r"(addr));
}

__device__ __forceinline__ void mma_f16(float* c, const uint32_t* a,
                                        const uint32_t* b) {
    asm volatile(
        "mma.sync.aligned.m16n8k16.row.col.f32.f16.f16.f32 "
        "{%0,%1,%2,%3},{%4,%5,%6,%7},{%8,%9},{%0,%1,%2,%3};"
        : "+f"(c[0]), "+f"(c[1]), "+f"(c[2]), "+f"(c[3])
        : "r"(a[0]), "r"(a[1]), "r"(a[2]), "r"(a[3]), "r"(b[0]), "r"(b[1]));
}

// ---------------------------------------------------------------------------
// Kernel 0: positional encoding table (fp64 args for exact sin/cos)
// ---------------------------------------------------------------------------
__global__ void pe_kernel() {
    int s = blockIdx.x;
    double pos = 6.283185307179586476925286766559 * (double)s;
    for (int h = threadIdx.x; h < H; h += blockDim.x) {
        int e = h & ~1;
        double dv = exp((double)e * (-log(10000.0) / (double)H));
        double a = pos * dv;
        g_pe[s * H + h] = (float)((h & 1) ? cos(a) : sin(a));
    }
}

// ---------------------------------------------------------------------------
// Fused weight transposes to half: w[K][N] -> wT[N][K]; z selects the matrix.
// ---------------------------------------------------------------------------
__global__ void transpose_all(const float* __restrict__ w0, __half* t0,
                              const float* __restrict__ w1, __half* t1,
                              const float* __restrict__ w2, __half* t2,
                              const float* __restrict__ w3, __half* t3) {
    int zz = blockIdx.z;
    const float* w; __half* wT; int Nc;
    if (zz == 0)      { w = w0; wT = t0; Nc = 3 * H; }
    else if (zz == 1) { w = w1; wT = t1; Nc = H; }
    else if (zz == 2) { w = w2; wT = t2; Nc = H; }
    else              { w = w3; wT = t3; Nc = H; }
    if (blockIdx.x * 32 >= Nc) return;

    __shared__ float t[32][33];
    int bx = blockIdx.x * 32, by = blockIdx.y * 32;
    int x = bx + threadIdx.x;
    for (int j = threadIdx.y; j < 32; j += 8)
        t[j][threadIdx.x] = w[(size_t)(by + j) * Nc + x];
    __syncthreads();
    int xo = by + threadIdx.x;
    for (int j = threadIdx.y; j < 32; j += 8)
        wT[(size_t)(bx + j) * H + xo] = __float2half_rn(t[threadIdx.x][j]);
}

// ---------------------------------------------------------------------------
// Block reduce helper (256 threads = 8 warps)
// ---------------------------------------------------------------------------
__device__ __forceinline__ float2 block_reduce2(float a, float b, float* sh) {
    int lane = threadIdx.x & 31, wid = threadIdx.x >> 5;
#pragma unroll
    for (int o = 16; o; o >>= 1) {
        a += __shfl_xor_sync(0xffffffffu, a, o);
        b += __shfl_xor_sync(0xffffffffu, b, o);
    }
    if (lane == 0) { sh[wid] = a; sh[8 + wid] = b; }
    __syncthreads();
    if (threadIdx.x == 0) {
        float s = 0.f, q = 0.f;
#pragma unroll
        for (int i = 0; i < 8; i++) { s += sh[i]; q += sh[8 + i]; }
        sh[0] = s; sh[8] = q;
    }
    __syncthreads();
    return make_float2(sh[0], sh[8]);
}

// ---------------------------------------------------------------------------
// x = LayerNorm(concat(cls, z^T) + pe); r' = s*NB+b layout (z is contiguous!)
// ---------------------------------------------------------------------------
__global__ void build_ln_kernel(const float* __restrict__ z,
                                const float* __restrict__ cls,
                                const float* __restrict__ lg,
                                const float* __restrict__ lb) {
    __shared__ float sh[16];
    int r = blockIdx.x;               // r' = s*NB + b
    int s = r / NB;
    int tid = threadIdx.x;
    int h0 = tid * 4;
    const float* src = (s == 0) ? (cls) : (z + (size_t)(r - NB) * H);

    float4 sv = *(const float4*)&src[h0];
    float4 pv = *(const float4*)&g_pe[s * H + h0];
    float4 v = make_float4(sv.x + pv.x, sv.y + pv.y, sv.z + pv.z, sv.w + pv.w);
    float sum = v.x + v.y + v.z + v.w;
    float sq  = v.x * v.x + v.y * v.y + v.z * v.z + v.w * v.w;

    float2 t = block_reduce2(sum, sq, sh);
    float mean = t.x * (1.f / H);
    float var  = t.y * (1.f / H) - mean * mean;
    float rstd = rsqrtf(var + 1e-5f);

    float4 gv = *(const float4*)&lg[h0];
    float4 bv = *(const float4*)&lb[h0];
    __half2* dh = (__half2*)&g_xh[(size_t)r * H + h0];
    dh[0] = __floats2half2_rn((v.x - mean) * rstd * gv.x + bv.x,
                              (v.y - mean) * rstd * gv.y + bv.y);
    dh[1] = __floats2half2_rn((v.z - mean) * rstd * gv.z + bv.z,
                              (v.w - mean) * rstd * gv.w + bv.w);
}

// ---------------------------------------------------------------------------
// zsa = LayerNorm(xh + sah); half in, half out. (layout-agnostic)
// ---------------------------------------------------------------------------
__global__ void res_ln_kernel(const float* __restrict__ lg,
                              const float* __restrict__ lb) {
    __shared__ float sh[16];
    int r = blockIdx.x;
    int tid = threadIdx.x;
    int h0 = tid * 4;
    size_t idx = (size_t)r * H + h0;

    uint2 xr = *(const uint2*)&g_xh[idx];
    uint2 ar = *(const uint2*)&g_sah[idx];
    float2 x0 = __half22float2(*(__half2*)&xr.x);
    float2 x1 = __half22float2(*(__half2*)&xr.y);
    float2 a0 = __half22float2(*(__half2*)&ar.x);
    float2 a1 = __half22float2(*(__half2*)&ar.y);
    float4 v = make_float4(x0.x + a0.x, x0.y + a0.y, x1.x + a1.x, x1.y + a1.y);
    float sum = v.x + v.y + v.z + v.w;
    float sq  = v.x * v.x + v.y * v.y + v.z * v.z + v.w * v.w;

    float2 t = block_reduce2(sum, sq, sh);
    float mean = t.x * (1.f / H);
    float var  = t.y * (1.f / H) - mean * mean;
    float rstd = rsqrtf(var + 1e-5f);

    float4 gv = *(const float4*)&lg[h0];
    float4 bv = *(const float4*)&lb[h0];
    __half2* dh = (__half2*)&g_zsah[idx];
    dh[0] = __floats2half2_rn((v.x - mean) * rstd * gv.x + bv.x,
                              (v.y - mean) * rstd * gv.y + bv.y);
    dh[1] = __floats2half2_rn((v.z - mean) * rstd * gv.z + bv.z,
                              (v.w - mean) * rstd * gv.w + bv.w);
}

// ---------------------------------------------------------------------------
// fp16 tensor-core GEMM: C[M,N] = A[M,1024] @ BT[N,1024]^T + bias
// CTA 128x128, 4 warps (64x64 warp tiles), K-chunk 64, XOR-8 swizzle,
// 3-stage cp.async, one barrier per k-iter, 2 CTAs/SM.
//   EPI 1: GELU->half  EPI 3: plain half out
//   EPI 4: half residual add, fp32 out (coalesced; layout matches output)
// ---------------------------------------------------------------------------
#define LOADG(kt, stage) do {                                                  \
    uint32_t st_ = (uint32_t)(stage) * STG2;                                   \
    const __half* aS_ = aBase + (kt) * KC;                                     \
    const __half* bS_ = bBase + (kt) * KC;                                     \
    _Pragma("unroll")                                                          \
    for (int i_ = 0; i_ < 8; i_++)                                             \
        cp16(dstA + st_ + (uint32_t)(i_ * 2048), aS_ + i_ * 16 * 1024);        \
    _Pragma("unroll")                                                          \
    for (int i_ = 0; i_ < 8; i_++)                                             \
        cp16(dstB + st_ + (uint32_t)(i_ * 2048), bS_ + i_ * 16 * 1024);        \
    asm volatile("cp.async.commit_group;");                                    \
} while (0)

template <int EPI>
__global__ void __launch_bounds__(GT, 2)
gemm_h(const __half* __restrict__ A, const __half* __restrict__ BT,
       const float* __restrict__ bias, void* __restrict__ Cv, int N,
       const __half* __restrict__ res) {
    extern __shared__ __align__(16) uint8_t smem[];
    const int tid = threadIdx.x;
    const int lane = tid & 31, wid = tid >> 5;
    const int mbase = blockIdx.y * 128, nbase = blockIdx.x * 128;
    const uint32_t sbase = (uint32_t)__cvta_generic_to_shared(smem);

    // loader bases (affine; swizzle XOR is per-thread constant)
    const int rowL = tid >> 3, cL = tid & 7;
    const uint32_t xorL = (uint32_t)((cL ^ (rowL & 7)) << 4);
    const __half* aBase = A  + (size_t)(mbase + rowL) * 1024 + cL * 8;
    const __half* bBase = BT + (size_t)(nbase + rowL) * 1024 + cL * 8;
    const uint32_t dstA = sbase + (uint32_t)(rowL * 128) + xorL;
    const uint32_t dstB = dstA + TILE2;

    const int warp_m0 = (wid >> 1) * 64;
    const int warp_n0 = (wid & 1) * 64;

    uint32_t aRow[4], bRow[4];
    int aSw[4], bSw[4];
    const int lr = lane & 15, lc = lane >> 4;
#pragma unroll
    for (int fm = 0; fm < 4; fm++) {
        int row = warp_m0 + fm * 16 + lr;
        aRow[fm] = (uint32_t)row * 128u;
        aSw[fm] = row & 7;
    }
#pragma unroll
    for (int p = 0; p < 4; p++) {
        int row = warp_n0 + p * 16 + lr;
        bRow[p] = (uint32_t)(TILE2 + row * 128);
        bSw[p] = row & 7;
    }

    float acc[4][8][4];
#pragma unroll
    for (int i = 0; i < 4; i++)
#pragma unroll
        for (int j = 0; j < 8; j++)
#pragma unroll
            for (int k = 0; k < 4; k++) acc[i][j][k] = 0.f;

    LOADG(0, 0);
    LOADG(1, 1);

#pragma unroll 1
    for (int kt = 0; kt < 16; kt++) {
        if (kt < 15)
            asm volatile("cp.async.wait_group 1;");
        else
            asm volatile("cp.async.wait_group 0;");
        __syncthreads();
        if (kt + 2 < 16) LOADG(kt + 2, (kt + 2) % NST2);

        uint32_t so = sbase + (uint32_t)(kt % NST2) * STG2;
#pragma unroll
        for (int kk = 0; kk < 4; kk++) {
            uint32_t a[4][4], b[8][2];
#pragma unroll
            for (int fm = 0; fm < 4; fm++)
                ldsm4(a[fm][0], a[fm][1], a[fm][2], a[fm][3],
                      so + aRow[fm] + (uint32_t)(((2 * kk + lc) ^ aSw[fm]) << 4));
#pragma unroll
            for (int p = 0; p < 4; p++) {
                uint32_t r0, r1, r2, r3;
                ldsm4(r0, r1, r2, r3,
                      so + bRow[p] + (uint32_t)(((2 * kk + lc) ^ bSw[p]) << 4));
                b[p * 2][0] = r0;     b[p * 2][1] = r2;
                b[p * 2 + 1][0] = r1; b[p * 2 + 1][1] = r3;
            }
#pragma unroll
            for (int fm = 0; fm < 4; fm++)
#pragma unroll
                for (int fn = 0; fn < 8; fn++)
                    mma_f16(acc[fm][fn], a[fm], b[fn]);
        }
    }

    // epilogue
    const int r4 = lane >> 2, c2 = (lane & 3) * 2;
#pragma unroll
    for (int fm = 0; fm < 4; fm++) {
#pragma unroll
        for (int half_ = 0; half_ < 2; half_++) {
            int m = mbase + warp_m0 + fm * 16 + half_ * 8 + r4;
#pragma unroll
            for (int fn = 0; fn < 8; fn++) {
                int n = nbase + warp_n0 + fn * 8 + c2;
                float2 bv = *(const float2*)&bias[n];
                float v0 = acc[fm][fn][half_ * 2 + 0] + bv.x;
                float v1 = acc[fm][fn][half_ * 2 + 1] + bv.y;
                if (EPI == 1) {
                    v0 = 0.5f * v0 * (1.f + erff(v0 * 0.70710678118654752440f));
                    v1 = 0.5f * v1 * (1.f + erff(v1 * 0.70710678118654752440f));
                    *(__half2*)&((__half*)Cv)[(size_t)m * N + n] =
                        __floats2half2_rn(v0, v1);
                } else if (EPI == 3) {
                    *(__half2*)&((__half*)Cv)[(size_t)m * N + n] =
                        __floats2half2_rn(v0, v1);
                } else {
                    __half2 rh = *(const __half2*)&res[(size_t)m * H + n];
                    float2 rv = __half22float2(rh);
                    *(float2*)&((float*)Cv)[(size_t)m * N + n] =
                        make_float2(rv.x + v0, rv.y + v1);
                }
            }
        }
    }
}

// ---------------------------------------------------------------------------
// Attention (merged): r' = s*NB+b layout. Row of token t, batch b: t*NB+b.
// blockIdx.x < NTILE -> banded query tile (s=1..149); == NTILE -> cls row.
// ---------------------------------------------------------------------------
__global__ void attn_kernel() {
    extern __shared__ float dyn[];
    __half* qs = (__half*)dyn;             // [QT][1024] half
    float*  sc = dyn + QT * H / 2;         // [QT][64] (banded) / [160] (cls)
    const int SCW = 64;

    int tile = blockIdx.x, b = blockIdx.y;
    int tid = threadIdx.x, lane = tid & 31, wid = tid >> 5;

    if (tile == NTILE) {
        // ---- cls row: q = token 0 (row b), keys t*NB+b ----
        const __half* qrow = g_qkvh + (size_t)b * 3 * H;
        for (int h = tid; h < H; h += 256) {
            float qv = __half2float(qrow[h]) * 0.03125f;
            qs[h] = __float2half_rn(qv);
        }
        __syncthreads();

        for (int t = wid; t < S1; t += 8) {
            const __half* krow = g_qkvh + ((size_t)t * NB + b) * 3 * H + H;
            float p = 0.f;
#pragma unroll
            for (int j = 0; j < 8; j++) {
                uint2 kw = *(const uint2*)&krow[lane * 4 + j * 128];
                uint2 qw = *(const uint2*)&qs[lane * 4 + j * 128];
                float2 ka = __half22float2(*(__half2*)&kw.x);
                float2 kb = __half22float2(*(__half2*)&kw.y);
                float2 qa = __half22float2(*(__half2*)&qw.x);
                float2 qb = __half22float2(*(__half2*)&qw.y);
                p += ka.x * qa.x + ka.y * qa.y + kb.x * qb.x + kb.y * qb.y;
            }
#pragma unroll
            for (int o = 16; o; o >>= 1) p += __shfl_xor_sync(0xffffffffu, p, o);
            if (lane == 0) sc[t] = p;
        }
        __syncthreads();

        if (tid < 32) {
            float m = -1e30f;
            for (int i = lane; i < S1; i += 32) m = fmaxf(m, sc[i]);
#pragma unroll
            for (int o = 16; o; o >>= 1)
                m = fmaxf(m, __shfl_xor_sync(0xffffffffu, m, o));
            float ss = 0.f;
            for (int i = lane; i < S1; i += 32) {
                float e = expf(sc[i] - m);
                sc[i] = e; ss += e;
            }
#pragma unroll
            for (int o = 16; o; o >>= 1) ss += __shfl_xor_sync(0xffffffffu, ss, o);
            float inv = 1.f / ss;
            for (int i = lane; i < S1; i += 32) sc[i] *= inv;
        }
        __syncthreads();

        int h0 = tid * 4;
        float4 acc = make_float4(0.f, 0.f, 0.f, 0.f);
        for (int t = 0; t < S1; t++) {
            const __half* vrow = g_qkvh + ((size_t)t * NB + b) * 3 * H + 2 * H;
            uint2 raw = *(const uint2*)&vrow[h0];
            float2 lo2 = __half22float2(*(__half2*)&raw.x);
            float2 hi2 = __half22float2(*(__half2*)&raw.y);
            float w = sc[t];
            acc.x += w * lo2.x; acc.y += w * lo2.y;
            acc.z += w * hi2.x; acc.w += w * hi2.y;
        }
        __half2* dst = (__half2*)&g_atth[(size_t)b * H + h0];
        dst[0] = __floats2half2_rn(acc.x, acc.y);
        dst[1] = __floats2half2_rn(acc.z, acc.w);
        return;
    }

    // ---- banded tile over s = s0 .. s0+nq-1 ----
    int s0 = 1 + tile * QT;
    int nq = min(QT, S1 - s0);

    int lo_u = s0 - WIN; if (lo_u < 0) lo_u = 0;
    int hi_u = s0 + nq - 1 + WIN; if (hi_u > S1) hi_u = S1;

    for (int idx = tid; idx < nq * H; idx += 256) {
        int q = idx >> 10, h = idx & 1023;
        const __half* qrow = g_qkvh + ((size_t)(s0 + q) * NB + b) * 3 * H;
        float qv = __half2float(qrow[h]) * 0.03125f;
        qs[q * H + h] = __float2half_rn(qv);
    }
    __syncthreads();

    // phase A: scores, 2 keys per warp iteration
    for (int t0 = lo_u + wid * 2; t0 < hi_u; t0 += 16) {
        int t1 = t0 + 1;
        bool has2 = (t1 < hi_u);
        const __half* k0 = g_qkvh + ((size_t)t0 * NB + b) * 3 * H + H;
        const __half* k1 = g_qkvh + ((size_t)(has2 ? t1 : t0) * NB + b) * 3 * H + H;
        float2 kr0[16], kr1[16];
#pragma unroll
        for (int j = 0; j < 8; j++) {
            uint2 w0 = *(const uint2*)&k0[lane * 4 + j * 128];
            uint2 w1 = *(const uint2*)&k1[lane * 4 + j * 128];
            kr0[j * 2]     = __half22float2(*(__half2*)&w0.x);
            kr0[j * 2 + 1] = __half22float2(*(__half2*)&w0.y);
            kr1[j * 2]     = __half22float2(*(__half2*)&w1.x);
            kr1[j * 2 + 1] = __half22float2(*(__half2*)&w1.y);
        }
        for (int q = 0; q < nq; q++) {
            const uint2* qrow = (const uint2*)&qs[q * H];
            float p0 = 0.f, p1 = 0.f;
#pragma unroll
            for (int j = 0; j < 8; j++) {
                uint2 qw = qrow[lane + j * 32];
                float2 qa = __half22float2(*(__half2*)&qw.x);
                float2 qb = __half22float2(*(__half2*)&qw.y);
                p0 += kr0[j * 2].x * qa.x + kr0[j * 2].y * qa.y +
                      kr0[j * 2 + 1].x * qb.x + kr0[j * 2 + 1].y * qb.y;
                p1 += kr1[j * 2].x * qa.x + kr1[j * 2].y * qa.y +
                      kr1[j * 2 + 1].x * qb.x + kr1[j * 2 + 1].y * qb.y;
            }
#pragma unroll
            for (int o = 16; o; o >>= 1) {
                p0 += __shfl_xor_sync(0xffffffffu, p0, o);
                p1 += __shfl_xor_sync(0xffffffffu, p1, o);
            }
            if (lane == 0) {
                sc[q * SCW + (t0 - lo_u)] = p0;
                if (has2) sc[q * SCW + (t1 - lo_u)] = p1;
            }
        }
    }
    __syncthreads();

    // phase B: softmax per query row (warp per row)
    for (int q = wid; q < nq; q += 8) {
        int s = s0 + q;
        int lo = s - WIN; if (lo < 0) lo = 0;
        int hi = s + WIN; if (hi > S1) hi = S1;
        int i0 = lo - lo_u, i1 = hi - lo_u;
        float m = -1e30f;
        for (int i = i0 + lane; i < i1; i += 32) m = fmaxf(m, sc[q * SCW + i]);
#pragma unroll
        for (int o = 16; o; o >>= 1) m = fmaxf(m, __shfl_xor_sync(0xffffffffu, m, o));
        float ss = 0.f;
        for (int i = i0 + lane; i < i1; i += 32) {
            float e = expf(sc[q * SCW + i] - m);
            sc[q * SCW + i] = e; ss += e;
        }
#pragma unroll
        for (int o = 16; o; o >>= 1) ss += __shfl_xor_sync(0xffffffffu, ss, o);
        float inv = 1.f / ss;
        for (int i = i0 + lane; i < i1; i += 32) sc[q * SCW + i] *= inv;
    }
    __syncthreads();

    // phase C: V accumulation. thread owns h0..h0+3 for all queries.
    int h0 = tid * 4;
    float4 acc[QT];
#pragma unroll
    for (int q = 0; q < QT; q++) acc[q] = make_float4(0.f, 0.f, 0.f, 0.f);

    for (int t = lo_u; t < hi_u; t++) {
        const __half* vrow = g_qkvh + ((size_t)t * NB + b) * 3 * H + 2 * H;
        uint2 raw = *(const uint2*)&vrow[h0];
        float2 lo2 = __half22float2(*(__half2*)&raw.x);
        float2 hi2 = __half22float2(*(__half2*)&raw.y);
        float4 v = make_float4(lo2.x, lo2.y, hi2.x, hi2.y);
#pragma unroll
        for (int q = 0; q < QT; q++) {
            if (q >= nq) break;
            int s = s0 + q;
            bool ok = (t >= s - WIN && t < s + WIN);
            if (ok) {
                float w = sc[q * SCW + (t - lo_u)];
                acc[q].x += w * v.x; acc[q].y += w * v.y;
                acc[q].z += w * v.z; acc[q].w += w * v.w;
            }
        }
    }
#pragma unroll
    for (int q = 0; q < QT; q++) {
        if (q >= nq) break;
        size_t r = (size_t)(s0 + q) * NB + b;
        __half2* dst = (__half2*)&g_atth[r * H + h0];
        dst[0] = __floats2half2_rn(acc[q].x, acc[q].y);
        dst[1] = __floats2half2_rn(acc[q].z, acc[q].w);
    }
}

// ---------------------------------------------------------------------------
// Launch
// ---------------------------------------------------------------------------
extern "C" void kernel_launch(void* const* d_in, const int* in_sizes, int n_in,
                              void* d_out, int out_size) {
    (void)in_sizes; (void)n_in; (void)out_size;
    const float* z     = (const float*)d_in[0];
    const float* cls   = (const float*)d_in[1];
    const float* ln_g  = (const float*)d_in[2];
    const float* ln_b  = (const float*)d_in[3];
    const float* w_qkv = (const float*)d_in[4];
    const float* b_qkv = (const float*)d_in[5];
    const float* w_o   = (const float*)d_in[6];
    const float* b_o   = (const float*)d_in[7];
    const float* w_m1  = (const float*)d_in[8];
    const float* b_m1  = (const float*)d_in[9];
    const float* w_m2  = (const float*)d_in[10];
    const float* b_m2  = (const float*)d_in[11];
    float* out = (float*)d_out;

    __half *pxh, *pqkvh, *patth, *psah, *pzsah, *ph1h;
    __half *pwqkvT, *pwoT, *pwm1T, *pwm2T;
    cudaGetSymbolAddress((void**)&pxh,   g_xh);
    cudaGetSymbolAddress((void**)&pqkvh, g_qkvh);
    cudaGetSymbolAddress((void**)&patth, g_atth);
    cudaGetSymbolAddress((void**)&psah,  g_sah);
    cudaGetSymbolAddress((void**)&pzsah, g_zsah);
    cudaGetSymbolAddress((void**)&ph1h,  g_h1h);
    cudaGetSymbolAddress((void**)&pwqkvT, g_wqkvT);
    cudaGetSymbolAddress((void**)&pwoT,   g_woT);
    cudaGetSymbolAddress((void**)&pwm1T,  g_wm1T);
    cudaGetSymbolAddress((void**)&pwm2T,  g_wm2T);

    const int ATTN_SMEM = QT * H * 2 + QT * 64 * 4;   // half q + fp32 scores
    static int attr_set = 0;
    if (!attr_set) {
        cudaFuncSetAttribute(attn_kernel,
                             cudaFuncAttributeMaxDynamicSharedMemorySize,
                             ATTN_SMEM);
        cudaFuncSetAttribute(gemm_h<1>,
                             cudaFuncAttributeMaxDynamicSharedMemorySize, GSMEM);
        cudaFuncSetAttribute(gemm_h<3>,
                             cudaFuncAttributeMaxDynamicSharedMemorySize, GSMEM);
        cudaFuncSetAttribute(gemm_h<4>,
                             cudaFuncAttributeMaxDynamicSharedMemorySize, GSMEM);
        attr_set = 1;
    }

    pe_kernel<<<S1, 256>>>();
    transpose_all<<<dim3(96, 32, 4), dim3(32, 8)>>>(w_qkv, pwqkvT, w_o, pwoT,
                                                    w_m1, pwm1T, w_m2, pwm2T);
    build_ln_kernel<<<NR, 256>>>(z, cls, ln_g, ln_b);

    // qkv = x @ w_qkv + b_qkv   (half out)
    gemm_h<3><<<dim3(3 * H / 128, NR / 128), GT, GSMEM>>>(pxh, pwqkvT, b_qkv, pqkvh, 3 * H, nullptr);
    // banded tiles + cls row in one launch
    attn_kernel<<<dim3(NTILE + 1, NB), 256, ATTN_SMEM>>>();
    // sa = att @ w_o + b_o      (half out)
    gemm_h<3><<<dim3(H / 128, NR / 128), GT, GSMEM>>>(patth, pwoT, b_o, psah, H, nullptr);
    res_ln_kernel<<<NR, 256>>>(ln_g, ln_b);
    // h1 = gelu(zsa @ w_m1 + b_m1)  (half out)
    gemm_h<1><<<dim3(H / 128, NR / 128), GT, GSMEM>>>(pzsah, pwm1T, b_m1, ph1h, H, nullptr);
    // out = zsah + h1 @ w_m2 + b_m2  (fp32 out, coalesced — already (s,b,h))
    gemm_h<4><<<dim3(H / 128, NR / 128), GT, GSMEM>>>(ph1h, pwm2T, b_m2, out, H, pzsah);
}

// round 17
// speedup vs baseline: 1.0460x; 1.0056x over previous
#include <cuda_runtime.h>
#include <cuda_fp16.h>
#include <math.h>
#include <stdint.h>

// ---------------------------------------------------------------------------
// TransformerEncoder block: H=1024, S1=150, B=128, banded attention (w=20).
// Round 16: R15 + (a) small GEMMs (N=1024) run 2-stage/3 CTAs-per-SM to cut
// wave-quantization tail; (b) attention phase A skips fully-masked key pairs.
// ---------------------------------------------------------------------------

#define H   1024
#define S1  150
#define NB  128
#define NR  (S1 * NB)      // 19200 rows, r' = s*NB + b
#define WIN 20
#define QT  16             // queries per banded attention block
#define NTILE (((S1 - 1) + QT - 1) / QT)   // 10 tiles over s=1..149

// GEMM tiling
#define KC     64                       // K per stage (halves)
#define TILE2  16384                    // 128 rows * 128 B
#define STG2   (2 * TILE2)              // A + B per stage
#define GSMEM_L (3 * STG2)              // 98304 (3-stage, 2 CTAs/SM)
#define GSMEM_S (2 * STG2)              // 65536 (2-stage, 3 CTAs/SM)
#define GT     128                      // 4 warps

// Scratch (allocation-free: device globals) — all fp16, rows r' = s*NB+b
__device__ float  g_pe [S1 * H];
__device__ __half g_xh [NR * H];
__device__ __half g_qkvh[NR * 3 * H];
__device__ __half g_atth[NR * H];
__device__ __half g_sah [NR * H];
__device__ __half g_zsah[NR * H];
__device__ __half g_h1h [NR * H];
__device__ __half g_wqkvT[3 * H * H];
__device__ __half g_woT  [H * H];
__device__ __half g_wm1T [H * H];
__device__ __half g_wm2T [H * H];

// ---------------------------------------------------------------------------
// PTX helpers
// ---------------------------------------------------------------------------
__device__ __forceinline__ void cp16(uint32_t saddr, const void* g) {
    asm volatile("cp.async.cg.shared.global [%0], [%1], 16;"
                 :: "r"(saddr), "l"(g));
}

__device__ __forceinline__ void ldsm4(uint32_t& r0, uint32_t& r1, uint32_t& r2,
                                      uint32_t& r3, uint32_t addr) {
    asm volatile("ldmatrix.sync.aligned.m8n8.x4.shared.b16 {%0,%1,%2,%3}, [%4];"
                 : "=r"(r0), "=r"(r1), "=r"(r2), "=r"(r3) : "r"(addr));
}

__device__ __forceinline__ void mma_f16(float* c, const uint32_t* a,
                                        const uint32_t* b) {
    asm volatile(
        "mma.sync.aligned.m16n8k16.row.col.f32.f16.f16.f32 "
        "{%0,%1,%2,%3},{%4,%5,%6,%7},{%8,%9},{%0,%1,%2,%3};"
        : "+f"(c[0]), "+f"(c[1]), "+f"(c[2]), "+f"(c[3])
        : "r"(a[0]), "r"(a[1]), "r"(a[2]), "r"(a[3]), "r"(b[0]), "r"(b[1]));
}

// ---------------------------------------------------------------------------
// Kernel 0: positional encoding table (fp64 args for exact sin/cos)
// ---------------------------------------------------------------------------
__global__ void pe_kernel() {
    int s = blockIdx.x;
    double pos = 6.283185307179586476925286766559 * (double)s;
    for (int h = threadIdx.x; h < H; h += blockDim.x) {
        int e = h & ~1;
        double dv = exp((double)e * (-log(10000.0) / (double)H));
        double a = pos * dv;
        g_pe[s * H + h] = (float)((h & 1) ? cos(a) : sin(a));
    }
}

// ---------------------------------------------------------------------------
// Fused weight transposes to half: w[K][N] -> wT[N][K]; z selects the matrix.
// ---------------------------------------------------------------------------
__global__ void transpose_all(const float* __restrict__ w0, __half* t0,
                              const float* __restrict__ w1, __half* t1,
                              const float* __restrict__ w2, __half* t2,
                              const float* __restrict__ w3, __half* t3) {
    int zz = blockIdx.z;
    const float* w; __half* wT; int Nc;
    if (zz == 0)      { w = w0; wT = t0; Nc = 3 * H; }
    else if (zz == 1) { w = w1; wT = t1; Nc = H; }
    else if (zz == 2) { w = w2; wT = t2; Nc = H; }
    else              { w = w3; wT = t3; Nc = H; }
    if (blockIdx.x * 32 >= Nc) return;

    __shared__ float t[32][33];
    int bx = blockIdx.x * 32, by = blockIdx.y * 32;
    int x = bx + threadIdx.x;
    for (int j = threadIdx.y; j < 32; j += 8)
        t[j][threadIdx.x] = w[(size_t)(by + j) * Nc + x];
    __syncthreads();
    int xo = by + threadIdx.x;
    for (int j = threadIdx.y; j < 32; j += 8)
        wT[(size_t)(bx + j) * H + xo] = __float2half_rn(t[threadIdx.x][j]);
}

// ---------------------------------------------------------------------------
// Block reduce helper (256 threads = 8 warps)
// ---------------------------------------------------------------------------
__device__ __forceinline__ float2 block_reduce2(float a, float b, float* sh) {
    int lane = threadIdx.x & 31, wid = threadIdx.x >> 5;
#pragma unroll
    for (int o = 16; o; o >>= 1) {
        a += __shfl_xor_sync(0xffffffffu, a, o);
        b += __shfl_xor_sync(0xffffffffu, b, o);
    }
    if (lane == 0) { sh[wid] = a; sh[8 + wid] = b; }
    __syncthreads();
    if (threadIdx.x == 0) {
        float s = 0.f, q = 0.f;
#pragma unroll
        for (int i = 0; i < 8; i++) { s += sh[i]; q += sh[8 + i]; }
        sh[0] = s; sh[8] = q;
    }
    __syncthreads();
    return make_float2(sh[0], sh[8]);
}

// ---------------------------------------------------------------------------
// x = LayerNorm(concat(cls, z^T) + pe); r' = s*NB+b layout (z contiguous)
// ---------------------------------------------------------------------------
__global__ void build_ln_kernel(const float* __restrict__ z,
                                const float* __restrict__ cls,
                                const float* __restrict__ lg,
                                const float* __restrict__ lb) {
    __shared__ float sh[16];
    int r = blockIdx.x;
    int s = r / NB;
    int tid = threadIdx.x;
    int h0 = tid * 4;
    const float* src = (s == 0) ? (cls) : (z + (size_t)(r - NB) * H);

    float4 sv = *(const float4*)&src[h0];
    float4 pv = *(const float4*)&g_pe[s * H + h0];
    float4 v = make_float4(sv.x + pv.x, sv.y + pv.y, sv.z + pv.z, sv.w + pv.w);
    float sum = v.x + v.y + v.z + v.w;
    float sq  = v.x * v.x + v.y * v.y + v.z * v.z + v.w * v.w;

    float2 t = block_reduce2(sum, sq, sh);
    float mean = t.x * (1.f / H);
    float var  = t.y * (1.f / H) - mean * mean;
    float rstd = rsqrtf(var + 1e-5f);

    float4 gv = *(const float4*)&lg[h0];
    float4 bv = *(const float4*)&lb[h0];
    __half2* dh = (__half2*)&g_xh[(size_t)r * H + h0];
    dh[0] = __floats2half2_rn((v.x - mean) * rstd * gv.x + bv.x,
                              (v.y - mean) * rstd * gv.y + bv.y);
    dh[1] = __floats2half2_rn((v.z - mean) * rstd * gv.z + bv.z,
                              (v.w - mean) * rstd * gv.w + bv.w);
}

// ---------------------------------------------------------------------------
// zsa = LayerNorm(xh + sah); half in, half out.
// ---------------------------------------------------------------------------
__global__ void res_ln_kernel(const float* __restrict__ lg,
                              const float* __restrict__ lb) {
    __shared__ float sh[16];
    int r = blockIdx.x;
    int tid = threadIdx.x;
    int h0 = tid * 4;
    size_t idx = (size_t)r * H + h0;

    uint2 xr = *(const uint2*)&g_xh[idx];
    uint2 ar = *(const uint2*)&g_sah[idx];
    float2 x0 = __half22float2(*(__half2*)&xr.x);
    float2 x1 = __half22float2(*(__half2*)&xr.y);
    float2 a0 = __half22float2(*(__half2*)&ar.x);
    float2 a1 = __half22float2(*(__half2*)&ar.y);
    float4 v = make_float4(x0.x + a0.x, x0.y + a0.y, x1.x + a1.x, x1.y + a1.y);
    float sum = v.x + v.y + v.z + v.w;
    float sq  = v.x * v.x + v.y * v.y + v.z * v.z + v.w * v.w;

    float2 t = block_reduce2(sum, sq, sh);
    float mean = t.x * (1.f / H);
    float var  = t.y * (1.f / H) - mean * mean;
    float rstd = rsqrtf(var + 1e-5f);

    float4 gv = *(const float4*)&lg[h0];
    float4 bv = *(const float4*)&lb[h0];
    __half2* dh = (__half2*)&g_zsah[idx];
    dh[0] = __floats2half2_rn((v.x - mean) * rstd * gv.x + bv.x,
                              (v.y - mean) * rstd * gv.y + bv.y);
    dh[1] = __floats2half2_rn((v.z - mean) * rstd * gv.z + bv.z,
                              (v.w - mean) * rstd * gv.w + bv.w);
}

// ---------------------------------------------------------------------------
// Shared GEMM pieces (CTA 128x128, 4 warps, XOR-8 swizzle).
// EPI 1: GELU->half  EPI 3: plain half  EPI 4: half residual + fp32 out
// ---------------------------------------------------------------------------
#define LOADG(kt, stage) do {                                                  \
    uint32_t st_ = (uint32_t)(stage) * STG2;                                   \
    const __half* aS_ = aBase + (kt) * KC;                                     \
    const __half* bS_ = bBase + (kt) * KC;                                     \
    _Pragma("unroll")                                                          \
    for (int i_ = 0; i_ < 8; i_++)                                             \
        cp16(dstA + st_ + (uint32_t)(i_ * 2048), aS_ + i_ * 16 * 1024);        \
    _Pragma("unroll")                                                          \
    for (int i_ = 0; i_ < 8; i_++)                                             \
        cp16(dstB + st_ + (uint32_t)(i_ * 2048), bS_ + i_ * 16 * 1024);        \
    asm volatile("cp.async.commit_group;");                                    \
} while (0)

#define GEMM_PRE()                                                             \
    extern __shared__ __align__(16) uint8_t smem[];                            \
    const int tid = threadIdx.x;                                               \
    const int lane = tid & 31, wid = tid >> 5;                                 \
    const int mbase = blockIdx.y * 128, nbase = blockIdx.x * 128;              \
    const uint32_t sbase = (uint32_t)__cvta_generic_to_shared(smem);           \
    const int rowL = tid >> 3, cL = tid & 7;                                   \
    const uint32_t xorL = (uint32_t)((cL ^ (rowL & 7)) << 4);                  \
    const __half* aBase = A  + (size_t)(mbase + rowL) * 1024 + cL * 8;         \
    const __half* bBase = BT + (size_t)(nbase + rowL) * 1024 + cL * 8;         \
    const uint32_t dstA = sbase + (uint32_t)(rowL * 128) + xorL;               \
    const uint32_t dstB = dstA + TILE2;                                        \
    const int warp_m0 = (wid >> 1) * 64;                                       \
    const int warp_n0 = (wid & 1) * 64;                                        \
    uint32_t aRow[4], bRow[4];                                                 \
    int aSw[4], bSw[4];                                                        \
    const int lr = lane & 15, lc = lane >> 4;                                  \
    _Pragma("unroll")                                                          \
    for (int fm = 0; fm < 4; fm++) {                                           \
        int row = warp_m0 + fm * 16 + lr;                                      \
        aRow[fm] = (uint32_t)row * 128u;                                       \
        aSw[fm] = row & 7;                                                     \
    }                                                                          \
    _Pragma("unroll")                                                          \
    for (int p = 0; p < 4; p++) {                                              \
        int row = warp_n0 + p * 16 + lr;                                       \
        bRow[p] = (uint32_t)(TILE2 + row * 128);                               \
        bSw[p] = row & 7;                                                      \
    }                                                                          \
    float acc[4][8][4];                                                        \
    _Pragma("unroll")                                                          \
    for (int i = 0; i < 4; i++)                                                \
        for (int j = 0; j < 8; j++)                                            \
            for (int k = 0; k < 4; k++) acc[i][j][k] = 0.f;

#define GEMM_STEP(so)                                                          \
    _Pragma("unroll")                                                          \
    for (int kk = 0; kk < 4; kk++) {                                           \
        uint32_t a[4][4], b[8][2];                                             \
        _Pragma("unroll")                                                      \
        for (int fm = 0; fm < 4; fm++)                                         \
            ldsm4(a[fm][0], a[fm][1], a[fm][2], a[fm][3],                      \
                  (so) + aRow[fm] + (uint32_t)(((2 * kk + lc) ^ aSw[fm]) << 4)); \
        _Pragma("unroll")                                                      \
        for (int p = 0; p < 4; p++) {                                          \
            uint32_t r0, r1, r2, r3;                                           \
            ldsm4(r0, r1, r2, r3,                                              \
                  (so) + bRow[p] + (uint32_t)(((2 * kk + lc) ^ bSw[p]) << 4)); \
            b[p * 2][0] = r0;     b[p * 2][1] = r2;                            \
            b[p * 2 + 1][0] = r1; b[p * 2 + 1][1] = r3;                        \
        }                                                                      \
        _Pragma("unroll")                                                      \
        for (int fm = 0; fm < 4; fm++)                                         \
            for (int fn = 0; fn < 8; fn++)                                     \
                mma_f16(acc[fm][fn], a[fm], b[fn]);                            \
    }

#define GEMM_EPI(EPI)                                                          \
    const int r4 = lane >> 2, c2 = (lane & 3) * 2;                             \
    _Pragma("unroll")                                                          \
    for (int fm = 0; fm < 4; fm++) {                                           \
        _Pragma("unroll")                                                      \
        for (int half_ = 0; half_ < 2; half_++) {                              \
            int m = mbase + warp_m0 + fm * 16 + half_ * 8 + r4;                \
            _Pragma("unroll")                                                  \
            for (int fn = 0; fn < 8; fn++) {                                   \
                int n = nbase + warp_n0 + fn * 8 + c2;                         \
                float2 bv = *(const float2*)&bias[n];                          \
                float v0 = acc[fm][fn][half_ * 2 + 0] + bv.x;                  \
                float v1 = acc[fm][fn][half_ * 2 + 1] + bv.y;                  \
                if (EPI == 1) {                                                \
                    v0 = 0.5f * v0 * (1.f + erff(v0 * 0.70710678f));           \
                    v1 = 0.5f * v1 * (1.f + erff(v1 * 0.70710678f));           \
                    *(__half2*)&((__half*)Cv)[(size_t)m * N + n] =             \
                        __floats2half2_rn(v0, v1);                             \
                } else if (EPI == 3) {                                         \
                    *(__half2*)&((__half*)Cv)[(size_t)m * N + n] =             \
                        __floats2half2_rn(v0, v1);                             \
                } else {                                                       \
                    __half2 rh = *(const __half2*)&res[(size_t)m * H + n];     \
                    float2 rv = __half22float2(rh);                            \
                    *(float2*)&((float*)Cv)[(size_t)m * N + n] =               \
                        make_float2(rv.x + v0, rv.y + v1);                     \
                }                                                              \
            }                                                                  \
        }                                                                      \
    }

// Large-grid GEMM: 3-stage, 2 CTAs/SM (qkv).
template <int EPI>
__global__ void __launch_bounds__(GT, 2)
gemm_h(const __half* __restrict__ A, const __half* __restrict__ BT,
       const float* __restrict__ bias, void* __restrict__ Cv, int N,
       const __half* __restrict__ res) {
    GEMM_PRE();
    LOADG(0, 0);
    LOADG(1, 1);
#pragma unroll 1
    for (int kt = 0; kt < 16; kt++) {
        if (kt < 15)
            asm volatile("cp.async.wait_group 1;");
        else
            asm volatile("cp.async.wait_group 0;");
        __syncthreads();
        if (kt + 2 < 16) LOADG(kt + 2, (kt + 2) % 3);
        uint32_t so = sbase + (uint32_t)(kt % 3) * STG2;
        GEMM_STEP(so);
    }
    GEMM_EPI(EPI);
}

// Small-grid GEMM: 2-stage, 3 CTAs/SM (N=1024 GEMMs; cuts wave tail).
template <int EPI>
__global__ void __launch_bounds__(GT, 3)
gemm_s(const __half* __restrict__ A, const __half* __restrict__ BT,
       const float* __restrict__ bias, void* __restrict__ Cv, int N,
       const __half* __restrict__ res) {
    GEMM_PRE();
    LOADG(0, 0);
#pragma unroll 1
    for (int kt = 0; kt < 16; kt++) {
        asm volatile("cp.async.wait_group 0;");
        __syncthreads();
        if (kt + 1 < 16) LOADG(kt + 1, (kt + 1) & 1);
        uint32_t so = sbase + (uint32_t)(kt & 1) * STG2;
        GEMM_STEP(so);
        __syncthreads();
    }
    GEMM_EPI(EPI);
}

// ---------------------------------------------------------------------------
// Attention (merged): r' = s*NB+b layout. blockIdx.x < NTILE -> banded tile;
// == NTILE -> cls row. Phase A skips fully-masked key pairs.
// ---------------------------------------------------------------------------
__global__ void attn_kernel() {
    extern __shared__ float dyn[];
    __half* qs = (__half*)dyn;             // [QT][1024] half
    float*  sc = dyn + QT * H / 2;         // [QT][64] (banded) / [160] (cls)
    const int SCW = 64;

    int tile = blockIdx.x, b = blockIdx.y;
    int tid = threadIdx.x, lane = tid & 31, wid = tid >> 5;

    if (tile == NTILE) {
        const __half* qrow = g_qkvh + (size_t)b * 3 * H;
        for (int h = tid; h < H; h += 256) {
            float qv = __half2float(qrow[h]) * 0.03125f;
            qs[h] = __float2half_rn(qv);
        }
        __syncthreads();

        for (int t = wid; t < S1; t += 8) {
            const __half* krow = g_qkvh + ((size_t)t * NB + b) * 3 * H + H;
            float p = 0.f;
#pragma unroll
            for (int j = 0; j < 8; j++) {
                uint2 kw = *(const uint2*)&krow[lane * 4 + j * 128];
                uint2 qw = *(const uint2*)&qs[lane * 4 + j * 128];
                float2 ka = __half22float2(*(__half2*)&kw.x);
                float2 kb = __half22float2(*(__half2*)&kw.y);
                float2 qa = __half22float2(*(__half2*)&qw.x);
                float2 qb = __half22float2(*(__half2*)&qw.y);
                p += ka.x * qa.x + ka.y * qa.y + kb.x * qb.x + kb.y * qb.y;
            }
#pragma unroll
            for (int o = 16; o; o >>= 1) p += __shfl_xor_sync(0xffffffffu, p, o);
            if (lane == 0) sc[t] = p;
        }
        __syncthreads();

        if (tid < 32) {
            float m = -1e30f;
            for (int i = lane; i < S1; i += 32) m = fmaxf(m, sc[i]);
#pragma unroll
            for (int o = 16; o; o >>= 1)
                m = fmaxf(m, __shfl_xor_sync(0xffffffffu, m, o));
            float ss = 0.f;
            for (int i = lane; i < S1; i += 32) {
                float e = expf(sc[i] - m);
                sc[i] = e; ss += e;
            }
#pragma unroll
            for (int o = 16; o; o >>= 1) ss += __shfl_xor_sync(0xffffffffu, ss, o);
            float inv = 1.f / ss;
            for (int i = lane; i < S1; i += 32) sc[i] *= inv;
        }
        __syncthreads();

        int h0 = tid * 4;
        float4 acc = make_float4(0.f, 0.f, 0.f, 0.f);
        for (int t = 0; t < S1; t++) {
            const __half* vrow = g_qkvh + ((size_t)t * NB + b) * 3 * H + 2 * H;
            uint2 raw = *(const uint2*)&vrow[h0];
            float2 lo2 = __half22float2(*(__half2*)&raw.x);
            float2 hi2 = __half22float2(*(__half2*)&raw.y);
            float w = sc[t];
            acc.x += w * lo2.x; acc.y += w * lo2.y;
            acc.z += w * hi2.x; acc.w += w * hi2.y;
        }
        __half2* dst = (__half2*)&g_atth[(size_t)b * H + h0];
        dst[0] = __floats2half2_rn(acc.x, acc.y);
        dst[1] = __floats2half2_rn(acc.z, acc.w);
        return;
    }

    // ---- banded tile over s = s0 .. s0+nq-1 ----
    int s0 = 1 + tile * QT;
    int nq = min(QT, S1 - s0);

    int lo_u = s0 - WIN; if (lo_u < 0) lo_u = 0;
    int hi_u = s0 + nq - 1 + WIN; if (hi_u > S1) hi_u = S1;

    for (int idx = tid; idx < nq * H; idx += 256) {
        int q = idx >> 10, h = idx & 1023;
        const __half* qrow = g_qkvh + ((size_t)(s0 + q) * NB + b) * 3 * H;
        float qv = __half2float(qrow[h]) * 0.03125f;
        qs[q * H + h] = __float2half_rn(qv);
    }
    __syncthreads();

    // phase A: scores, 2 keys per warp iteration; skip fully masked q.
    for (int t0 = lo_u + wid * 2; t0 < hi_u; t0 += 16) {
        int t1 = t0 + 1;
        bool has2 = (t1 < hi_u);
        const __half* k0 = g_qkvh + ((size_t)t0 * NB + b) * 3 * H + H;
        const __half* k1 = g_qkvh + ((size_t)(has2 ? t1 : t0) * NB + b) * 3 * H + H;
        float2 kr0[16], kr1[16];
#pragma unroll
        for (int j = 0; j < 8; j++) {
            uint2 w0 = *(const uint2*)&k0[lane * 4 + j * 128];
            uint2 w1 = *(const uint2*)&k1[lane * 4 + j * 128];
            kr0[j * 2]     = __half22float2(*(__half2*)&w0.x);
            kr0[j * 2 + 1] = __half22float2(*(__half2*)&w0.y);
            kr1[j * 2]     = __half22float2(*(__half2*)&w1.x);
            kr1[j * 2 + 1] = __half22float2(*(__half2*)&w1.y);
        }
        for (int q = 0; q < nq; q++) {
            int s = s0 + q;
            bool v0 = (t0 >= s - WIN) && (t0 < s + WIN);
            bool v1 = has2 && (t1 >= s - WIN) && (t1 < s + WIN);
            if (!v0 && !v1) continue;
            const uint2* qrow = (const uint2*)&qs[q * H];
            float p0 = 0.f, p1 = 0.f;
#pragma unroll
            for (int j = 0; j < 8; j++) {
                uint2 qw = qrow[lane + j * 32];
                float2 qa = __half22float2(*(__half2*)&qw.x);
                float2 qb = __half22float2(*(__half2*)&qw.y);
                p0 += kr0[j * 2].x * qa.x + kr0[j * 2].y * qa.y +
                      kr0[j * 2 + 1].x * qb.x + kr0[j * 2 + 1].y * qb.y;
                p1 += kr1[j * 2].x * qa.x + kr1[j * 2].y * qa.y +
                      kr1[j * 2 + 1].x * qb.x + kr1[j * 2 + 1].y * qb.y;
            }
#pragma unroll
            for (int o = 16; o; o >>= 1) {
                p0 += __shfl_xor_sync(0xffffffffu, p0, o);
                p1 += __shfl_xor_sync(0xffffffffu, p1, o);
            }
            if (lane == 0) {
                if (v0) sc[q * SCW + (t0 - lo_u)] = p0;
                if (v1) sc[q * SCW + (t1 - lo_u)] = p1;
            }
        }
    }
    __syncthreads();

    // phase B: softmax per query row (warp per row)
    for (int q = wid; q < nq; q += 8) {
        int s = s0 + q;
        int lo = s - WIN; if (lo < 0) lo = 0;
        int hi = s + WIN; if (hi > S1) hi = S1;
        int i0 = lo - lo_u, i1 = hi - lo_u;
        float m = -1e30f;
        for (int i = i0 + lane; i < i1; i += 32) m = fmaxf(m, sc[q * SCW + i]);
#pragma unroll
        for (int o = 16; o; o >>= 1) m = fmaxf(m, __shfl_xor_sync(0xffffffffu, m, o));
        float ss = 0.f;
        for (int i = i0 + lane; i < i1; i += 32) {
            float e = expf(sc[q * SCW + i] - m);
            sc[q * SCW + i] = e; ss += e;
        }
#pragma unroll
        for (int o = 16; o; o >>= 1) ss += __shfl_xor_sync(0xffffffffu, ss, o);
        float inv = 1.f / ss;
        for (int i = i0 + lane; i < i1; i += 32) sc[q * SCW + i] *= inv;
    }
    __syncthreads();

    // phase C: V accumulation. thread owns h0..h0+3 for all queries.
    int h0 = tid * 4;
    float4 acc[QT];
#pragma unroll
    for (int q = 0; q < QT; q++) acc[q] = make_float4(0.f, 0.f, 0.f, 0.f);

    for (int t = lo_u; t < hi_u; t++) {
        const __half* vrow = g_qkvh + ((size_t)t * NB + b) * 3 * H + 2 * H;
        uint2 raw = *(const uint2*)&vrow[h0];
        float2 lo2 = __half22float2(*(__half2*)&raw.x);
        float2 hi2 = __half22float2(*(__half2*)&raw.y);
        float4 v = make_float4(lo2.x, lo2.y, hi2.x, hi2.y);
#pragma unroll
        for (int q = 0; q < QT; q++) {
            if (q >= nq) break;
            int s = s0 + q;
            bool ok = (t >= s - WIN && t < s + WIN);
            if (ok) {
                float w = sc[q * SCW + (t - lo_u)];
                acc[q].x += w * v.x; acc[q].y += w * v.y;
                acc[q].z += w * v.z; acc[q].w += w * v.w;
            }
        }
    }
#pragma unroll
    for (int q = 0; q < QT; q++) {
        if (q >= nq) break;
        size_t r = (size_t)(s0 + q) * NB + b;
        __half2* dst = (__half2*)&g_atth[r * H + h0];
        dst[0] = __floats2half2_rn(acc[q].x, acc[q].y);
        dst[1] = __floats2half2_rn(acc[q].z, acc[q].w);
    }
}

// ---------------------------------------------------------------------------
// Launch
// ---------------------------------------------------------------------------
extern "C" void kernel_launch(void* const* d_in, const int* in_sizes, int n_in,
                              void* d_out, int out_size) {
    (void)in_sizes; (void)n_in; (void)out_size;
    const float* z     = (const float*)d_in[0];
    const float* cls   = (const float*)d_in[1];
    const float* ln_g  = (const float*)d_in[2];
    const float* ln_b  = (const float*)d_in[3];
    const float* w_qkv = (const float*)d_in[4];
    const float* b_qkv = (const float*)d_in[5];
    const float* w_o   = (const float*)d_in[6];
    const float* b_o   = (const float*)d_in[7];
    const float* w_m1  = (const float*)d_in[8];
    const float* b_m1  = (const float*)d_in[9];
    const float* w_m2  = (const float*)d_in[10];
    const float* b_m2  = (const float*)d_in[11];
    float* out = (float*)d_out;

    __half *pxh, *pqkvh, *patth, *psah, *pzsah, *ph1h;
    __half *pwqkvT, *pwoT, *pwm1T, *pwm2T;
    cudaGetSymbolAddress((void**)&pxh,   g_xh);
    cudaGetSymbolAddress((void**)&pqkvh, g_qkvh);
    cudaGetSymbolAddress((void**)&patth, g_atth);
    cudaGetSymbolAddress((void**)&psah,  g_sah);
    cudaGetSymbolAddress((void**)&pzsah, g_zsah);
    cudaGetSymbolAddress((void**)&ph1h,  g_h1h);
    cudaGetSymbolAddress((void**)&pwqkvT, g_wqkvT);
    cudaGetSymbolAddress((void**)&pwoT,   g_woT);
    cudaGetSymbolAddress((void**)&pwm1T,  g_wm1T);
    cudaGetSymbolAddress((void**)&pwm2T,  g_wm2T);

    const int ATTN_SMEM = QT * H * 2 + QT * 64 * 4;
    static int attr_set = 0;
    if (!attr_set) {
        cudaFuncSetAttribute(attn_kernel,
                             cudaFuncAttributeMaxDynamicSharedMemorySize,
                             ATTN_SMEM);
        cudaFuncSetAttribute(gemm_h<3>,
                             cudaFuncAttributeMaxDynamicSharedMemorySize, GSMEM_L);
        cudaFuncSetAttribute(gemm_s<1>,
                             cudaFuncAttributeMaxDynamicSharedMemorySize, GSMEM_S);
        cudaFuncSetAttribute(gemm_s<3>,
                             cudaFuncAttributeMaxDynamicSharedMemorySize, GSMEM_S);
        cudaFuncSetAttribute(gemm_s<4>,
                             cudaFuncAttributeMaxDynamicSharedMemorySize, GSMEM_S);
        attr_set = 1;
    }

    pe_kernel<<<S1, 256>>>();
    transpose_all<<<dim3(96, 32, 4), dim3(32, 8)>>>(w_qkv, pwqkvT, w_o, pwoT,
                                                    w_m1, pwm1T, w_m2, pwm2T);
    build_ln_kernel<<<NR, 256>>>(z, cls, ln_g, ln_b);

    // qkv = x @ w_qkv + b_qkv   (large grid: 3-stage, 2 CTAs/SM)
    gemm_h<3><<<dim3(3 * H / 128, NR / 128), GT, GSMEM_L>>>(pxh, pwqkvT, b_qkv, pqkvh, 3 * H, nullptr);
    // banded tiles + cls row in one launch
    attn_kernel<<<dim3(NTILE + 1, NB), 256, ATTN_SMEM>>>();
    // sa = att @ w_o + b_o      (small grid: 2-stage, 3 CTAs/SM)
    gemm_s<3><<<dim3(H / 128, NR / 128), GT, GSMEM_S>>>(patth, pwoT, b_o, psah, H, nullptr);
    res_ln_kernel<<<NR, 256>>>(ln_g, ln_b);
    // h1 = gelu(zsa @ w_m1 + b_m1)
    gemm_s<1><<<dim3(H / 128, NR / 128), GT, GSMEM_S>>>(pzsah, pwm1T, b_m1, ph1h, H, nullptr);
    // out = zsah + h1 @ w_m2 + b_m2  (fp32 out, coalesced)
    gemm_s<4><<<dim3(H / 128, NR / 128), GT, GSMEM_S>>>(ph1h, pwm2T, b_m2, out, H, pzsah);
}